// round 10
// baseline (speedup 1.0000x reference)
#include <cuda_runtime.h>
#include <cuda_bf16.h>
#include <math.h>
#include <stdint.h>

#define Bsz 4
#define Nn 1024
#define Cc 512
#define Hh 8
#define DH 64
#define BH 32
#define INNER 512
#define Ff 160   // 64 (E) + 64 (S) + 32 (H)
#define LDA 132  // smem stride for 128-wide tiles (k_qkv)
#define LDP 68   // smem stride for 64-wide tiles (k_proj)

typedef unsigned long long u64;

// ---- scratch (static device allocations; no runtime alloc) ----
__device__ float g_Q[BH * Nn * DH];
__device__ float g_K[BH * Nn * DH];
__device__ float g_V[BH * Nn * DH];
__device__ float g_FQ[BH * Nn * Ff];
__device__ float g_FK[BH * Nn * Ff];
__device__ float g_QA[BH * Nn];
__device__ float g_QU[BH * Nn];
__device__ float g_KB[BH * Nn];
__device__ float g_KV[BH * Nn];
__device__ float g_O[Bsz * Nn * INNER];

__device__ __forceinline__ float softplusf(float x) {
    return (x > 20.f) ? x : log1pf(expf(x));
}
__device__ __forceinline__ float fast_sqrt(float x) {
    float r; asm("sqrt.approx.f32 %0, %1;" : "=f"(r) : "f"(x)); return r;
}
__device__ __forceinline__ float fast_rcp(float x) {
    float r; asm("rcp.approx.f32 %0, %1;" : "=f"(r) : "f"(x)); return r;
}

// ---- packed f32x2 FMA ----
__device__ __forceinline__ void fma2(u64& d, u64 a, u64 b) {
    asm("fma.rn.f32x2 %0, %1, %2, %0;" : "+l"(d) : "l"(a), "l"(b));
}
__device__ __forceinline__ u64 pack2(float lo, float hi) {
    u64 r; asm("mov.b64 %0, {%1, %2};" : "=l"(r) : "f"(lo), "f"(hi)); return r;
}
__device__ __forceinline__ void unpack2(u64 v, float& lo, float& hi) {
    asm("mov.b64 {%0, %1}, %2;" : "=f"(lo), "=f"(hi) : "l"(v));
}

#define MICRO8X8(ACC2, a0, a1, b0, b1) {                                      \
    u64 q0 = pack2(b0.x, b0.y), q1 = pack2(b0.z, b0.w);                       \
    u64 q2 = pack2(b1.x, b1.y), q3 = pack2(b1.z, b1.w);                       \
    u64 ar;                                                                   \
    ar = pack2(a0.x, a0.x); fma2(ACC2[0][0],ar,q0); fma2(ACC2[0][1],ar,q1); fma2(ACC2[0][2],ar,q2); fma2(ACC2[0][3],ar,q3); \
    ar = pack2(a0.y, a0.y); fma2(ACC2[1][0],ar,q0); fma2(ACC2[1][1],ar,q1); fma2(ACC2[1][2],ar,q2); fma2(ACC2[1][3],ar,q3); \
    ar = pack2(a0.z, a0.z); fma2(ACC2[2][0],ar,q0); fma2(ACC2[2][1],ar,q1); fma2(ACC2[2][2],ar,q2); fma2(ACC2[2][3],ar,q3); \
    ar = pack2(a0.w, a0.w); fma2(ACC2[3][0],ar,q0); fma2(ACC2[3][1],ar,q1); fma2(ACC2[3][2],ar,q2); fma2(ACC2[3][3],ar,q3); \
    ar = pack2(a1.x, a1.x); fma2(ACC2[4][0],ar,q0); fma2(ACC2[4][1],ar,q1); fma2(ACC2[4][2],ar,q2); fma2(ACC2[4][3],ar,q3); \
    ar = pack2(a1.y, a1.y); fma2(ACC2[5][0],ar,q0); fma2(ACC2[5][1],ar,q1); fma2(ACC2[5][2],ar,q2); fma2(ACC2[5][3],ar,q3); \
    ar = pack2(a1.z, a1.z); fma2(ACC2[6][0],ar,q0); fma2(ACC2[6][1],ar,q1); fma2(ACC2[6][2],ar,q2); fma2(ACC2[6][3],ar,q3); \
    ar = pack2(a1.w, a1.w); fma2(ACC2[7][0],ar,q0); fma2(ACC2[7][1],ar,q1); fma2(ACC2[7][2],ar,q2); fma2(ACC2[7][3],ar,q3); \
}

#define MICRO4X4F2(ACC2, a, b) {                                              \
    u64 b01 = pack2(b.x, b.y), b23 = pack2(b.z, b.w);                         \
    u64 ar;                                                                   \
    ar = pack2(a.x, a.x); fma2(ACC2[0][0], ar, b01); fma2(ACC2[0][1], ar, b23); \
    ar = pack2(a.y, a.y); fma2(ACC2[1][0], ar, b01); fma2(ACC2[1][1], ar, b23); \
    ar = pack2(a.z, a.z); fma2(ACC2[2][0], ar, b01); fma2(ACC2[2][1], ar, b23); \
    ar = pack2(a.w, a.w); fma2(ACC2[3][0], ar, b01); fma2(ACC2[3][1], ar, b23); \
}

// ============================================================
// K1: qkv = x @ w_qkv^T -> per-head Q/K/V. 128x128 tile, 8x8 micro.
// ============================================================
__global__ __launch_bounds__(256) void k_qkv(const float* __restrict__ x,
                                             const float* __restrict__ w) {
    __shared__ float As[2][16][LDA];
    __shared__ float Bs[2][16][LDA];
    int tid = threadIdx.x;
    int ty = tid >> 4, tx = tid & 15;
    int srow = tid >> 1, sq = (tid & 1) * 2;
    const float* Ap = x + ((size_t)(blockIdx.y * 128) + srow) * Cc + sq * 4;
    const float* Bp = w + ((size_t)(blockIdx.x * 128) + srow) * Cc + sq * 4;
    u64 acc2[8][4] = {};
    float4 a0v, a1v, b0v, b1v;

#define Q_LDG(KT) \
    a0v = *(const float4*)(Ap + (KT) * 16);     a1v = *(const float4*)(Ap + (KT) * 16 + 4); \
    b0v = *(const float4*)(Bp + (KT) * 16);     b1v = *(const float4*)(Bp + (KT) * 16 + 4);
#define Q_STS(BUF) \
    As[BUF][sq*4+0][srow]=a0v.x; As[BUF][sq*4+1][srow]=a0v.y; As[BUF][sq*4+2][srow]=a0v.z; As[BUF][sq*4+3][srow]=a0v.w; \
    As[BUF][sq*4+4][srow]=a1v.x; As[BUF][sq*4+5][srow]=a1v.y; As[BUF][sq*4+6][srow]=a1v.z; As[BUF][sq*4+7][srow]=a1v.w; \
    Bs[BUF][sq*4+0][srow]=b0v.x; Bs[BUF][sq*4+1][srow]=b0v.y; Bs[BUF][sq*4+2][srow]=b0v.z; Bs[BUF][sq*4+3][srow]=b0v.w; \
    Bs[BUF][sq*4+4][srow]=b1v.x; Bs[BUF][sq*4+5][srow]=b1v.y; Bs[BUF][sq*4+6][srow]=b1v.z; Bs[BUF][sq*4+7][srow]=b1v.w;
#define Q_COMP(BUF) \
    _Pragma("unroll") \
    for (int kk = 0; kk < 16; kk++) { \
        float4 a0 = *(const float4*)&As[BUF][kk][ty * 8]; \
        float4 a1 = *(const float4*)&As[BUF][kk][ty * 8 + 4]; \
        float4 b0 = *(const float4*)&Bs[BUF][kk][tx * 8]; \
        float4 b1 = *(const float4*)&Bs[BUF][kk][tx * 8 + 4]; \
        MICRO8X8(acc2, a0, a1, b0, b1) \
    }

    Q_LDG(0) Q_STS(0)
    __syncthreads();
    for (int kt = 0; kt < 32; kt += 2) {
        if (kt + 1 < 32) { Q_LDG(kt + 1) }
        Q_COMP(0)
        if (kt + 1 < 32) { Q_STS(1) }
        __syncthreads();
        if (kt + 1 < 32) {
            if (kt + 2 < 32) { Q_LDG(kt + 2) }
            Q_COMP(1)
            if (kt + 2 < 32) { Q_STS(0) }
            __syncthreads();
        }
    }

    float acc[8][8];
#pragma unroll
    for (int i = 0; i < 8; i++)
#pragma unroll
        for (int p = 0; p < 4; p++) unpack2(acc2[i][p], acc[i][2 * p], acc[i][2 * p + 1]);

    int m0 = blockIdx.y * 128 + ty * 8;
    int n0 = blockIdx.x * 128 + tx * 8;
#pragma unroll
    for (int i = 0; i < 8; i++) {
        int m = m0 + i;
        int b = m / Nn, n = m % Nn;
#pragma unroll
        for (int j = 0; j < 8; j++) {
            int jc = n0 + j;
            int part = jc / INNER, r = jc % INNER;
            int h = r / DH, d = r % DH;
            float* dst = (part == 0) ? g_Q : ((part == 1) ? g_K : g_V);
            dst[((size_t)(b * Hh + h) * Nn + n) * DH + d] = acc[i][j];
        }
    }
}

// ============================================================
// K2: per-token metric embeddings (unchanged)
// ============================================================
__global__ __launch_bounds__(256) void k_embed(const float* __restrict__ we, const float* __restrict__ be,
                                               const float* __restrict__ ws, const float* __restrict__ bs,
                                               const float* __restrict__ wh, const float* __restrict__ bhh) {
    __shared__ float W[Ff][65];
    __shared__ float bias[Ff];
    __shared__ float qr[4][64];
    __shared__ float raw[4][Ff];
    int tid = threadIdx.x;
    for (int i = tid; i < 64 * 64; i += 256) { W[i / 64][i % 64] = we[i]; W[64 + i / 64][i % 64] = ws[i]; }
    for (int i = tid; i < 32 * 64; i += 256) W[128 + i / 64][i % 64] = wh[i];
    for (int i = tid; i < Ff; i += 256) bias[i] = (i < 64) ? be[i] : ((i < 128) ? bs[i - 64] : bhh[i - 128]);
    const float* src = (blockIdx.y == 0) ? g_Q : g_K;
    int tok0 = blockIdx.x * 4;
    for (int i = tid; i < 4 * 64; i += 256) qr[i / 64][i % 64] = src[(size_t)(tok0 + i / 64) * 64 + (i % 64)];
    __syncthreads();
    for (int i = tid; i < 4 * Ff; i += 256) {
        int tt = i / Ff, j = i % Ff;
        float s = bias[j];
#pragma unroll 8
        for (int c = 0; c < 64; c++) s += qr[tt][c] * W[j][c];
        raw[tt][j] = s;
    }
    __syncthreads();
    int w = tid >> 5, lane = tid & 31;
    if (w < 4) {
        int tt = w;
        float an = 0.f, sn = 0.f, un = 0.f;
        for (int j = lane; j < 64; j += 32) { float v = raw[tt][j]; an += v * v; }
        for (int j = 64 + lane; j < 128; j += 32) { float v = raw[tt][j]; sn += v * v; }
        {
            int j = 128 + lane;
            float th = tanhf(raw[tt][j]);
            raw[tt][j] = th;
            un += th * th;
        }
#pragma unroll
        for (int o = 16; o; o >>= 1) {
            an += __shfl_xor_sync(0xffffffffu, an, o);
            sn += __shfl_xor_sync(0xffffffffu, sn, o);
            un += __shfl_xor_sync(0xffffffffu, un, o);
        }
        float inv = 1.f / fmaxf(sqrtf(sn), 1e-12f);
        __syncwarp();
        float* Fdst = (blockIdx.y == 0) ? g_FQ : g_FK;
        int tok = tok0 + tt;
        for (int j = lane; j < Ff; j += 32) {
            float v = raw[tt][j];
            if (j >= 64 && j < 128) v *= inv;
            Fdst[(size_t)tok * Ff + j] = v;
        }
        if (lane == 0) {
            if (blockIdx.y == 0) { g_QA[tok] = an; g_QU[tok] = un; }
            else                 { g_KB[tok] = an; g_KV[tok] = un; }
        }
    }
}

// ============================================================
// K3: FUSED attention: score GEMM (staged groups) + online softmax + P@V
// (unchanged from R9)
// ============================================================
#define O_ARES 0
#define O_BS   10880
#define O_PS   13056
#define O_VS   17408
#define O_AN   21760
#define O_UN   21824
#define O_BN   21888
#define O_VN   21952
#define ATT_SMEM_BYTES (22016 * 4)

#define FMA16(ACC, a, b) \
    ACC[0][0] += a.x * b.x; ACC[0][1] += a.x * b.y; ACC[0][2] += a.x * b.z; ACC[0][3] += a.x * b.w; \
    ACC[1][0] += a.y * b.x; ACC[1][1] += a.y * b.y; ACC[1][2] += a.y * b.z; ACC[1][3] += a.y * b.w; \
    ACC[2][0] += a.z * b.x; ACC[2][1] += a.z * b.y; ACC[2][2] += a.z * b.z; ACC[2][3] += a.z * b.w; \
    ACC[3][0] += a.w * b.x; ACC[3][1] += a.w * b.y; ACC[3][2] += a.w * b.z; ACC[3][3] += a.w * b.w;

#define G2STEP(E, VB) { \
    accO[0][0]+=pa0.E*VB.x; accO[0][1]+=pa0.E*VB.y; accO[0][2]+=pa0.E*VB.z; accO[0][3]+=pa0.E*VB.w; \
    accO[1][0]+=pa1.E*VB.x; accO[1][1]+=pa1.E*VB.y; accO[1][2]+=pa1.E*VB.z; accO[1][3]+=pa1.E*VB.w; \
    accO[2][0]+=pa2.E*VB.x; accO[2][1]+=pa2.E*VB.y; accO[2][2]+=pa2.E*VB.z; accO[2][3]+=pa2.E*VB.w; \
    accO[3][0]+=pa3.E*VB.x; accO[3][1]+=pa3.E*VB.y; accO[3][2]+=pa3.E*VB.z; accO[3][3]+=pa3.E*VB.w; }

__global__ __launch_bounds__(256, 2) void k_attn(const float* __restrict__ alpha,
                                                 const float* __restrict__ beta,
                                                 const float* __restrict__ gamma,
                                                 const float* __restrict__ temp) {
    extern __shared__ float sm[];
    int tid = threadIdx.x;
    int ty = tid >> 4, tx = tid & 15;
    int brow = tid >> 2, bq = tid & 3;
    int bh = blockIdx.y;
    int row0 = blockIdx.x * 64;

    const float* FQb = g_FQ + ((size_t)bh * Nn + row0) * Ff;
    const float* FKb = g_FK + (size_t)bh * Nn * Ff;
    const float* Vb  = g_V + (size_t)bh * Nn * DH;

#pragma unroll
    for (int t = 0; t < 10; t++) {
        int idx = tid + 256 * t;
        int r = idx / 40, q4 = idx % 40;
        float4 v = *(const float4*)(FQb + (size_t)r * Ff + q4 * 4);
        sm[O_ARES + (q4 * 4 + 0) * 68 + r] = v.x;
        sm[O_ARES + (q4 * 4 + 1) * 68 + r] = v.y;
        sm[O_ARES + (q4 * 4 + 2) * 68 + r] = v.z;
        sm[O_ARES + (q4 * 4 + 3) * 68 + r] = v.w;
    }
    if (tid < 64) {
        sm[O_AN + tid] = g_QA[bh * Nn + row0 + tid];
        sm[O_UN + tid] = g_QU[bh * Nn + row0 + tid];
    }

    float cE = softplusf(alpha[0]);
    float cS = softplusf(beta[0]);
    float cH = softplusf(gamma[0]);
    float negInvT = -1.f / softplusf(temp[0]);

    float m_[4], l_[4], accO[4][4];
#pragma unroll
    for (int i = 0; i < 4; i++) {
        m_[i] = -1e30f; l_[i] = 0.f;
#pragma unroll
        for (int j = 0; j < 4; j++) accO[i][j] = 0.f;
    }
    __syncthreads();

    for (int kt = 0; kt < 16; kt++) {
        int col0 = kt * 64;
        const float* Bp = FKb + (size_t)(col0 + brow) * Ff + bq * 4;

        {
            float4 v = *(const float4*)(Bp);
            sm[O_BS + (bq * 4 + 0) * 68 + brow] = v.x;
            sm[O_BS + (bq * 4 + 1) * 68 + brow] = v.y;
            sm[O_BS + (bq * 4 + 2) * 68 + brow] = v.z;
            sm[O_BS + (bq * 4 + 3) * 68 + brow] = v.w;
        }
        if (tid < 64) {
            sm[O_BN + tid] = g_KB[bh * Nn + col0 + tid];
            sm[O_VN + tid] = g_KV[bh * Nn + col0 + tid];
        }
        __syncthreads();

        float acc[4][4] = {};
        float s_[4][4];
        float4 bvreg;

#pragma unroll
        for (int c = 0; c < 10; c++) {
            if (c < 9) bvreg = *(const float4*)(Bp + (c + 1) * 16);
            int bb = O_BS + (c & 1) * 1088;
#pragma unroll
            for (int kk = 0; kk < 16; kk++) {
                float4 a = *(const float4*)&sm[O_ARES + (c * 16 + kk) * 68 + ty * 4];
                float4 b = *(const float4*)&sm[bb + kk * 68 + tx * 4];
                FMA16(acc, a, b)
            }
            if (c < 9) {
                int b2 = O_BS + ((c + 1) & 1) * 1088;
                sm[b2 + (bq * 4 + 0) * 68 + brow] = bvreg.x;
                sm[b2 + (bq * 4 + 1) * 68 + brow] = bvreg.y;
                sm[b2 + (bq * 4 + 2) * 68 + brow] = bvreg.z;
                sm[b2 + (bq * 4 + 3) * 68 + brow] = bvreg.w;
            }
            if (c == 3) {
#pragma unroll
                for (int i = 0; i < 4; i++) {
                    float an = sm[O_AN + ty * 4 + i];
#pragma unroll
                    for (int j = 0; j < 4; j++) {
                        float bn = sm[O_BN + tx * 4 + j];
                        s_[i][j] = cE * fast_sqrt(fmaxf(an + bn - 2.f * acc[i][j], 1e-12f));
                        acc[i][j] = 0.f;
                    }
                }
            }
            if (c == 7) {
#pragma unroll
                for (int i = 0; i < 4; i++)
#pragma unroll
                    for (int j = 0; j < 4; j++) {
                        float x = fminf(fmaxf(acc[i][j], -1.f + 1e-6f), 1.f - 1e-6f);
                        float ax = fabsf(x);
                        float poly = fmaf(ax, fmaf(ax, fmaf(ax, -0.0187293f, 0.0742610f), -0.2121144f), 1.5707288f);
                        float rr = fast_sqrt(1.f - ax) * poly;
                        float dS = (x >= 0.f) ? rr : (3.14159265358979f - rr);
                        s_[i][j] += cS * dS;
                        acc[i][j] = 0.f;
                    }
            }
            if (c == 9) {
#pragma unroll
                for (int i = 0; i < 4; i++) {
                    float un = sm[O_UN + ty * 4 + i];
                    float one_m_un = 1.f - un;
#pragma unroll
                    for (int j = 0; j < 4; j++) {
                        float vn = sm[O_VN + tx * 4 + j];
                        float dns = fmaxf(un + vn - 2.f * acc[i][j], 0.f);
                        float denom = one_m_un * (1.f - vn) + 1e-8f;
                        float t = fmaxf(2.f * dns * fast_rcp(denom), 1e-6f);
                        float sh = fast_sqrt(t * (t + 2.f));
                        float dHp = __logf(1.f + t + sh);
                        s_[i][j] = negInvT * (s_[i][j] + cH * dHp);
                    }
                }
            }
            if (c < 9) __syncthreads();
        }

        float4 vr[4];
#pragma unroll
        for (int t = 0; t < 4; t++) {
            int idx = tid + 256 * t;
            int c = idx >> 4, dq = idx & 15;
            vr[t] = *(const float4*)(Vb + (size_t)(col0 + c) * DH + dq * 4);
        }

#pragma unroll
        for (int i = 0; i < 4; i++) {
            float rm = fmaxf(fmaxf(s_[i][0], s_[i][1]), fmaxf(s_[i][2], s_[i][3]));
#pragma unroll
            for (int o = 1; o < 16; o <<= 1) rm = fmaxf(rm, __shfl_xor_sync(0xffffffffu, rm, o));
            float mn = fmaxf(m_[i], rm);
            float sc = __expf(m_[i] - mn);
            float p0 = __expf(s_[i][0] - mn);
            float p1 = __expf(s_[i][1] - mn);
            float p2 = __expf(s_[i][2] - mn);
            float p3 = __expf(s_[i][3] - mn);
            float rs = (p0 + p1) + (p2 + p3);
#pragma unroll
            for (int o = 1; o < 16; o <<= 1) rs += __shfl_xor_sync(0xffffffffu, rs, o);
            l_[i] = l_[i] * sc + rs;
            m_[i] = mn;
            accO[i][0] *= sc; accO[i][1] *= sc; accO[i][2] *= sc; accO[i][3] *= sc;
            *(float4*)&sm[O_PS + (ty * 4 + i) * 68 + tx * 4] = make_float4(p0, p1, p2, p3);
        }
#pragma unroll
        for (int t = 0; t < 4; t++) {
            int idx = tid + 256 * t;
            int c = idx >> 4, dq = idx & 15;
            *(float4*)&sm[O_VS + c * 68 + dq * 4] = vr[t];
        }
        __syncthreads();

#pragma unroll
        for (int c4 = 0; c4 < 16; c4++) {
            float4 pa0 = *(const float4*)&sm[O_PS + (ty * 4 + 0) * 68 + c4 * 4];
            float4 pa1 = *(const float4*)&sm[O_PS + (ty * 4 + 1) * 68 + c4 * 4];
            float4 pa2 = *(const float4*)&sm[O_PS + (ty * 4 + 2) * 68 + c4 * 4];
            float4 pa3 = *(const float4*)&sm[O_PS + (ty * 4 + 3) * 68 + c4 * 4];
            float4 vb0 = *(const float4*)&sm[O_VS + (c4 * 4 + 0) * 68 + tx * 4];
            float4 vb1 = *(const float4*)&sm[O_VS + (c4 * 4 + 1) * 68 + tx * 4];
            float4 vb2 = *(const float4*)&sm[O_VS + (c4 * 4 + 2) * 68 + tx * 4];
            float4 vb3 = *(const float4*)&sm[O_VS + (c4 * 4 + 3) * 68 + tx * 4];
            G2STEP(x, vb0)
            G2STEP(y, vb1)
            G2STEP(z, vb2)
            G2STEP(w, vb3)
        }
        __syncthreads();
    }

    int b = bh / Hh, h = bh % Hh;
#pragma unroll
    for (int i = 0; i < 4; i++) {
        float inv = fast_rcp(l_[i]);
        float4 o = make_float4(accO[i][0] * inv, accO[i][1] * inv,
                               accO[i][2] * inv, accO[i][3] * inv);
        *(float4*)&g_O[((size_t)(b * Nn + row0 + ty * 4 + i)) * INNER + h * DH + tx * 4] = o;
    }
}

// ============================================================
// K6: final projection. 64x64 tile, 4x4 micro (grid 512, high occupancy).
// ============================================================
__global__ __launch_bounds__(256) void k_proj(const float* __restrict__ wp,
                                              const float* __restrict__ bp,
                                              float* __restrict__ out) {
    __shared__ float As[2][16][LDP];
    __shared__ float Bs[2][16][LDP];
    int tid = threadIdx.x, ty = tid >> 4, tx = tid & 15;
    int arow = tid >> 2, aq = tid & 3;
    const float* Abase = g_O + (size_t)(blockIdx.y * 64) * INNER;
    const float* Bbase = wp + (size_t)(blockIdx.x * 64) * INNER;
    u64 acc2[4][2] = {};
    float4 av, bv;

#define PR_LDG(KT) \
    av = *(const float4*)(Abase + (size_t)arow * INNER + (KT) * 16 + aq * 4); \
    bv = *(const float4*)(Bbase + (size_t)arow * INNER + (KT) * 16 + aq * 4);
#define PR_STS(BUF) \
    As[BUF][aq * 4 + 0][arow] = av.x; As[BUF][aq * 4 + 1][arow] = av.y; \
    As[BUF][aq * 4 + 2][arow] = av.z; As[BUF][aq * 4 + 3][arow] = av.w; \
    Bs[BUF][aq * 4 + 0][arow] = bv.x; Bs[BUF][aq * 4 + 1][arow] = bv.y; \
    Bs[BUF][aq * 4 + 2][arow] = bv.z; Bs[BUF][aq * 4 + 3][arow] = bv.w;
#define PR_COMP(BUF) \
    _Pragma("unroll") \
    for (int kk = 0; kk < 16; kk++) { \
        float4 a = *(const float4*)&As[BUF][kk][ty * 4]; \
        float4 b = *(const float4*)&Bs[BUF][kk][tx * 4]; \
        MICRO4X4F2(acc2, a, b) \
    }

    PR_LDG(0) PR_STS(0)
    __syncthreads();
    for (int kt = 0; kt < 32; kt += 2) {
        if (kt + 1 < 32) { PR_LDG(kt + 1) }
        PR_COMP(0)
        if (kt + 1 < 32) { PR_STS(1) }
        __syncthreads();
        if (kt + 1 < 32) {
            if (kt + 2 < 32) { PR_LDG(kt + 2) }
            PR_COMP(1)
            if (kt + 2 < 32) { PR_STS(0) }
            __syncthreads();
        }
    }

    float acc[4][4];
#pragma unroll
    for (int i = 0; i < 4; i++) {
        unpack2(acc2[i][0], acc[i][0], acc[i][1]);
        unpack2(acc2[i][1], acc[i][2], acc[i][3]);
    }
    int m0 = blockIdx.y * 64 + ty * 4;
    int n0 = blockIdx.x * 64 + tx * 4;
#pragma unroll
    for (int i = 0; i < 4; i++) {
        float4 o = make_float4(acc[i][0] + bp[n0 + 0], acc[i][1] + bp[n0 + 1],
                               acc[i][2] + bp[n0 + 2], acc[i][3] + bp[n0 + 3]);
        *(float4*)&out[(size_t)(m0 + i) * Cc + n0] = o;
    }
}

extern "C" void kernel_launch(void* const* d_in, const int* in_sizes, int n_in,
                              void* d_out, int out_size) {
    const float* x      = (const float*)d_in[0];
    const float* w_qkv  = (const float*)d_in[1];
    const float* w_proj = (const float*)d_in[2];
    const float* b_proj = (const float*)d_in[3];
    const float* w_e    = (const float*)d_in[4];
    const float* b_e    = (const float*)d_in[5];
    const float* w_s    = (const float*)d_in[6];
    const float* b_s    = (const float*)d_in[7];
    const float* w_h    = (const float*)d_in[8];
    const float* b_h    = (const float*)d_in[9];
    const float* alpha  = (const float*)d_in[10];
    const float* beta   = (const float*)d_in[11];
    const float* gamma  = (const float*)d_in[12];
    const float* temp   = (const float*)d_in[13];
    float* out = (float*)d_out;

    cudaFuncSetAttribute(k_attn, cudaFuncAttributeMaxDynamicSharedMemorySize, ATT_SMEM_BYTES);

    k_qkv<<<dim3(12, 32), 256>>>(x, w_qkv);
    k_embed<<<dim3(BH * Nn / 4, 2), 256>>>(w_e, b_e, w_s, b_s, w_h, b_h);
    k_attn<<<dim3(16, BH), 256, ATT_SMEM_BYTES>>>(alpha, beta, gamma, temp);
    k_proj<<<dim3(8, 64), 256>>>(w_proj, b_proj, out);
}

// round 11
// speedup vs baseline: 1.0063x; 1.0063x over previous
#include <cuda_runtime.h>
#include <cuda_bf16.h>
#include <math.h>
#include <stdint.h>

#define Bsz 4
#define Nn 1024
#define Cc 512
#define Hh 8
#define DH 64
#define BH 32
#define INNER 512
#define Ff 160   // 64 (E) + 64 (S) + 32 (H)
#define LDA 132  // smem stride for 128-wide tiles

typedef unsigned long long u64;

// ---- scratch (static device allocations; no runtime alloc) ----
__device__ float g_Q[BH * Nn * DH];
__device__ float g_K[BH * Nn * DH];
__device__ float g_V[BH * Nn * DH];
__device__ float g_FQ[BH * Nn * Ff];
__device__ float g_FK[BH * Nn * Ff];
__device__ float g_QA[BH * Nn];
__device__ float g_QU[BH * Nn];
__device__ float g_KB[BH * Nn];
__device__ float g_KV[BH * Nn];
__device__ float g_O[Bsz * Nn * INNER];

__device__ __forceinline__ float softplusf(float x) {
    return (x > 20.f) ? x : log1pf(expf(x));
}
__device__ __forceinline__ float fast_sqrt(float x) {
    float r; asm("sqrt.approx.f32 %0, %1;" : "=f"(r) : "f"(x)); return r;
}
__device__ __forceinline__ float fast_rcp(float x) {
    float r; asm("rcp.approx.f32 %0, %1;" : "=f"(r) : "f"(x)); return r;
}

// ---- packed f32x2 FMA ----
__device__ __forceinline__ void fma2(u64& d, u64 a, u64 b) {
    asm("fma.rn.f32x2 %0, %1, %2, %0;" : "+l"(d) : "l"(a), "l"(b));
}
__device__ __forceinline__ u64 pack2(float lo, float hi) {
    u64 r; asm("mov.b64 %0, {%1, %2};" : "=l"(r) : "f"(lo), "f"(hi)); return r;
}
__device__ __forceinline__ void unpack2(u64 v, float& lo, float& hi) {
    asm("mov.b64 {%0, %1}, %2;" : "=f"(lo), "=f"(hi) : "l"(v));
}

#define MICRO8X8(ACC2, a0, a1, b0, b1) {                                      \
    u64 q0 = pack2(b0.x, b0.y), q1 = pack2(b0.z, b0.w);                       \
    u64 q2 = pack2(b1.x, b1.y), q3 = pack2(b1.z, b1.w);                       \
    u64 ar;                                                                   \
    ar = pack2(a0.x, a0.x); fma2(ACC2[0][0],ar,q0); fma2(ACC2[0][1],ar,q1); fma2(ACC2[0][2],ar,q2); fma2(ACC2[0][3],ar,q3); \
    ar = pack2(a0.y, a0.y); fma2(ACC2[1][0],ar,q0); fma2(ACC2[1][1],ar,q1); fma2(ACC2[1][2],ar,q2); fma2(ACC2[1][3],ar,q3); \
    ar = pack2(a0.z, a0.z); fma2(ACC2[2][0],ar,q0); fma2(ACC2[2][1],ar,q1); fma2(ACC2[2][2],ar,q2); fma2(ACC2[2][3],ar,q3); \
    ar = pack2(a0.w, a0.w); fma2(ACC2[3][0],ar,q0); fma2(ACC2[3][1],ar,q1); fma2(ACC2[3][2],ar,q2); fma2(ACC2[3][3],ar,q3); \
    ar = pack2(a1.x, a1.x); fma2(ACC2[4][0],ar,q0); fma2(ACC2[4][1],ar,q1); fma2(ACC2[4][2],ar,q2); fma2(ACC2[4][3],ar,q3); \
    ar = pack2(a1.y, a1.y); fma2(ACC2[5][0],ar,q0); fma2(ACC2[5][1],ar,q1); fma2(ACC2[5][2],ar,q2); fma2(ACC2[5][3],ar,q3); \
    ar = pack2(a1.z, a1.z); fma2(ACC2[6][0],ar,q0); fma2(ACC2[6][1],ar,q1); fma2(ACC2[6][2],ar,q2); fma2(ACC2[6][3],ar,q3); \
    ar = pack2(a1.w, a1.w); fma2(ACC2[7][0],ar,q0); fma2(ACC2[7][1],ar,q1); fma2(ACC2[7][2],ar,q2); fma2(ACC2[7][3],ar,q3); \
}

// ============================================================
// K1: qkv = x @ w_qkv^T -> per-head Q/K/V. 128x128 tile, 8x8 micro.
// ============================================================
__global__ __launch_bounds__(256) void k_qkv(const float* __restrict__ x,
                                             const float* __restrict__ w) {
    __shared__ float As[2][16][LDA];
    __shared__ float Bs[2][16][LDA];
    int tid = threadIdx.x;
    int ty = tid >> 4, tx = tid & 15;
    int srow = tid >> 1, sq = (tid & 1) * 2;
    const float* Ap = x + ((size_t)(blockIdx.y * 128) + srow) * Cc + sq * 4;
    const float* Bp = w + ((size_t)(blockIdx.x * 128) + srow) * Cc + sq * 4;
    u64 acc2[8][4] = {};
    float4 a0v, a1v, b0v, b1v;

#define Q_LDG(KT) \
    a0v = *(const float4*)(Ap + (KT) * 16);     a1v = *(const float4*)(Ap + (KT) * 16 + 4); \
    b0v = *(const float4*)(Bp + (KT) * 16);     b1v = *(const float4*)(Bp + (KT) * 16 + 4);
#define Q_STS(BUF) \
    As[BUF][sq*4+0][srow]=a0v.x; As[BUF][sq*4+1][srow]=a0v.y; As[BUF][sq*4+2][srow]=a0v.z; As[BUF][sq*4+3][srow]=a0v.w; \
    As[BUF][sq*4+4][srow]=a1v.x; As[BUF][sq*4+5][srow]=a1v.y; As[BUF][sq*4+6][srow]=a1v.z; As[BUF][sq*4+7][srow]=a1v.w; \
    Bs[BUF][sq*4+0][srow]=b0v.x; Bs[BUF][sq*4+1][srow]=b0v.y; Bs[BUF][sq*4+2][srow]=b0v.z; Bs[BUF][sq*4+3][srow]=b0v.w; \
    Bs[BUF][sq*4+4][srow]=b1v.x; Bs[BUF][sq*4+5][srow]=b1v.y; Bs[BUF][sq*4+6][srow]=b1v.z; Bs[BUF][sq*4+7][srow]=b1v.w;
#define Q_COMP(BUF) \
    _Pragma("unroll") \
    for (int kk = 0; kk < 16; kk++) { \
        float4 a0 = *(const float4*)&As[BUF][kk][ty * 8]; \
        float4 a1 = *(const float4*)&As[BUF][kk][ty * 8 + 4]; \
        float4 b0 = *(const float4*)&Bs[BUF][kk][tx * 8]; \
        float4 b1 = *(const float4*)&Bs[BUF][kk][tx * 8 + 4]; \
        MICRO8X8(acc2, a0, a1, b0, b1) \
    }

    Q_LDG(0) Q_STS(0)
    __syncthreads();
    for (int kt = 0; kt < 32; kt += 2) {
        if (kt + 1 < 32) { Q_LDG(kt + 1) }
        Q_COMP(0)
        if (kt + 1 < 32) { Q_STS(1) }
        __syncthreads();
        if (kt + 1 < 32) {
            if (kt + 2 < 32) { Q_LDG(kt + 2) }
            Q_COMP(1)
            if (kt + 2 < 32) { Q_STS(0) }
            __syncthreads();
        }
    }

    float acc[8][8];
#pragma unroll
    for (int i = 0; i < 8; i++)
#pragma unroll
        for (int p = 0; p < 4; p++) unpack2(acc2[i][p], acc[i][2 * p], acc[i][2 * p + 1]);

    int m0 = blockIdx.y * 128 + ty * 8;
    int n0 = blockIdx.x * 128 + tx * 8;
#pragma unroll
    for (int i = 0; i < 8; i++) {
        int m = m0 + i;
        int b = m / Nn, n = m % Nn;
#pragma unroll
        for (int j = 0; j < 8; j++) {
            int jc = n0 + j;
            int part = jc / INNER, r = jc % INNER;
            int h = r / DH, d = r % DH;
            float* dst = (part == 0) ? g_Q : ((part == 1) ? g_K : g_V);
            dst[((size_t)(b * Hh + h) * Nn + n) * DH + d] = acc[i][j];
        }
    }
}

// ============================================================
// K2: per-token metric embeddings (unchanged)
// ============================================================
__global__ __launch_bounds__(256) void k_embed(const float* __restrict__ we, const float* __restrict__ be,
                                               const float* __restrict__ ws, const float* __restrict__ bs,
                                               const float* __restrict__ wh, const float* __restrict__ bhh) {
    __shared__ float W[Ff][65];
    __shared__ float bias[Ff];
    __shared__ float qr[4][64];
    __shared__ float raw[4][Ff];
    int tid = threadIdx.x;
    for (int i = tid; i < 64 * 64; i += 256) { W[i / 64][i % 64] = we[i]; W[64 + i / 64][i % 64] = ws[i]; }
    for (int i = tid; i < 32 * 64; i += 256) W[128 + i / 64][i % 64] = wh[i];
    for (int i = tid; i < Ff; i += 256) bias[i] = (i < 64) ? be[i] : ((i < 128) ? bs[i - 64] : bhh[i - 128]);
    const float* src = (blockIdx.y == 0) ? g_Q : g_K;
    int tok0 = blockIdx.x * 4;
    for (int i = tid; i < 4 * 64; i += 256) qr[i / 64][i % 64] = src[(size_t)(tok0 + i / 64) * 64 + (i % 64)];
    __syncthreads();
    for (int i = tid; i < 4 * Ff; i += 256) {
        int tt = i / Ff, j = i % Ff;
        float s = bias[j];
#pragma unroll 8
        for (int c = 0; c < 64; c++) s += qr[tt][c] * W[j][c];
        raw[tt][j] = s;
    }
    __syncthreads();
    int w = tid >> 5, lane = tid & 31;
    if (w < 4) {
        int tt = w;
        float an = 0.f, sn = 0.f, un = 0.f;
        for (int j = lane; j < 64; j += 32) { float v = raw[tt][j]; an += v * v; }
        for (int j = 64 + lane; j < 128; j += 32) { float v = raw[tt][j]; sn += v * v; }
        {
            int j = 128 + lane;
            float th = tanhf(raw[tt][j]);
            raw[tt][j] = th;
            un += th * th;
        }
#pragma unroll
        for (int o = 16; o; o >>= 1) {
            an += __shfl_xor_sync(0xffffffffu, an, o);
            sn += __shfl_xor_sync(0xffffffffu, sn, o);
            un += __shfl_xor_sync(0xffffffffu, un, o);
        }
        float inv = 1.f / fmaxf(sqrtf(sn), 1e-12f);
        __syncwarp();
        float* Fdst = (blockIdx.y == 0) ? g_FQ : g_FK;
        int tok = tok0 + tt;
        for (int j = lane; j < Ff; j += 32) {
            float v = raw[tt][j];
            if (j >= 64 && j < 128) v *= inv;
            Fdst[(size_t)tok * Ff + j] = v;
        }
        if (lane == 0) {
            if (blockIdx.y == 0) { g_QA[tok] = an; g_QU[tok] = un; }
            else                 { g_KB[tok] = an; g_KV[tok] = un; }
        }
    }
}

// ============================================================
// K3: FUSED attention, 32-wide k-feature chunks (5 chunks, group-aligned)
// ============================================================
#define O_ARES 0        // 160 x 68  (q features transposed [k][row])
#define O_BS   10880    // 2 x 32 x 68 (k-feature chunks, [k][row])
#define O_PS   15232    // 64 x 68  (P tile [row][c])
#define O_VS   19584    // 64 x 68  (V tile [c][d])
#define O_AN   23936
#define O_UN   24000
#define O_BN   24064
#define O_VN   24128
#define ATT_SMEM_BYTES (24192 * 4)   // 96768 B

#define FMA16(ACC, a, b) \
    ACC[0][0] += a.x * b.x; ACC[0][1] += a.x * b.y; ACC[0][2] += a.x * b.z; ACC[0][3] += a.x * b.w; \
    ACC[1][0] += a.y * b.x; ACC[1][1] += a.y * b.y; ACC[1][2] += a.y * b.z; ACC[1][3] += a.y * b.w; \
    ACC[2][0] += a.z * b.x; ACC[2][1] += a.z * b.y; ACC[2][2] += a.z * b.z; ACC[2][3] += a.z * b.w; \
    ACC[3][0] += a.w * b.x; ACC[3][1] += a.w * b.y; ACC[3][2] += a.w * b.z; ACC[3][3] += a.w * b.w;

#define G2STEP(E, VB) { \
    accO[0][0]+=pa0.E*VB.x; accO[0][1]+=pa0.E*VB.y; accO[0][2]+=pa0.E*VB.z; accO[0][3]+=pa0.E*VB.w; \
    accO[1][0]+=pa1.E*VB.x; accO[1][1]+=pa1.E*VB.y; accO[1][2]+=pa1.E*VB.z; accO[1][3]+=pa1.E*VB.w; \
    accO[2][0]+=pa2.E*VB.x; accO[2][1]+=pa2.E*VB.y; accO[2][2]+=pa2.E*VB.z; accO[2][3]+=pa2.E*VB.w; \
    accO[3][0]+=pa3.E*VB.x; accO[3][1]+=pa3.E*VB.y; accO[3][2]+=pa3.E*VB.z; accO[3][3]+=pa3.E*VB.w; }

__global__ __launch_bounds__(256, 2) void k_attn(const float* __restrict__ alpha,
                                                 const float* __restrict__ beta,
                                                 const float* __restrict__ gamma,
                                                 const float* __restrict__ temp) {
    extern __shared__ float sm[];
    int tid = threadIdx.x;
    int ty = tid >> 4, tx = tid & 15;
    int brow = tid >> 2, bq = tid & 3;
    int bh = blockIdx.y;
    int row0 = blockIdx.x * 64;

    const float* FQb = g_FQ + ((size_t)bh * Nn + row0) * Ff;
    const float* FKb = g_FK + (size_t)bh * Nn * Ff;
    const float* Vb  = g_V + (size_t)bh * Nn * DH;

    // one-time: load q-feature tile transposed into resident smem + q norms
#pragma unroll
    for (int t = 0; t < 10; t++) {
        int idx = tid + 256 * t;
        int r = idx / 40, q4 = idx % 40;
        float4 v = *(const float4*)(FQb + (size_t)r * Ff + q4 * 4);
        sm[O_ARES + (q4 * 4 + 0) * 68 + r] = v.x;
        sm[O_ARES + (q4 * 4 + 1) * 68 + r] = v.y;
        sm[O_ARES + (q4 * 4 + 2) * 68 + r] = v.z;
        sm[O_ARES + (q4 * 4 + 3) * 68 + r] = v.w;
    }
    if (tid < 64) {
        sm[O_AN + tid] = g_QA[bh * Nn + row0 + tid];
        sm[O_UN + tid] = g_QU[bh * Nn + row0 + tid];
    }

    float cE = softplusf(alpha[0]);
    float cS = softplusf(beta[0]);
    float cH = softplusf(gamma[0]);
    float negInvT = -1.f / softplusf(temp[0]);

    float m_[4], l_[4], accO[4][4];
#pragma unroll
    for (int i = 0; i < 4; i++) {
        m_[i] = -1e30f; l_[i] = 0.f;
#pragma unroll
        for (int j = 0; j < 4; j++) accO[i][j] = 0.f;
    }
    __syncthreads();

    for (int kt = 0; kt < 16; kt++) {
        int col0 = kt * 64;
        const float* Bp = FKb + (size_t)(col0 + brow) * Ff + bq * 4;

        // prologue: stage chunk 0 (k 0..31) + k norms
        {
            float4 v0 = *(const float4*)(Bp);
            float4 v1 = *(const float4*)(Bp + 16);
            sm[O_BS + (bq * 4 + 0) * 68 + brow] = v0.x;
            sm[O_BS + (bq * 4 + 1) * 68 + brow] = v0.y;
            sm[O_BS + (bq * 4 + 2) * 68 + brow] = v0.z;
            sm[O_BS + (bq * 4 + 3) * 68 + brow] = v0.w;
            sm[O_BS + (bq * 4 + 16) * 68 + brow] = v1.x;
            sm[O_BS + (bq * 4 + 17) * 68 + brow] = v1.y;
            sm[O_BS + (bq * 4 + 18) * 68 + brow] = v1.z;
            sm[O_BS + (bq * 4 + 19) * 68 + brow] = v1.w;
        }
        if (tid < 64) {
            sm[O_BN + tid] = g_KB[bh * Nn + col0 + tid];
            sm[O_VN + tid] = g_KV[bh * Nn + col0 + tid];
        }
        __syncthreads();

        float acc[4][4] = {};
        float s_[4][4];
        float4 bvreg0, bvreg1;

#pragma unroll
        for (int c = 0; c < 5; c++) {
            if (c < 4) {
                bvreg0 = *(const float4*)(Bp + (c + 1) * 32);
                bvreg1 = *(const float4*)(Bp + (c + 1) * 32 + 16);
            }
            int bb = O_BS + (c & 1) * 2176;
#pragma unroll
            for (int kk = 0; kk < 32; kk++) {
                float4 a = *(const float4*)&sm[O_ARES + (c * 32 + kk) * 68 + ty * 4];
                float4 b = *(const float4*)&sm[bb + kk * 68 + tx * 4];
                FMA16(acc, a, b)
            }
            if (c < 4) {
                int b2 = O_BS + ((c + 1) & 1) * 2176;
                sm[b2 + (bq * 4 + 0) * 68 + brow] = bvreg0.x;
                sm[b2 + (bq * 4 + 1) * 68 + brow] = bvreg0.y;
                sm[b2 + (bq * 4 + 2) * 68 + brow] = bvreg0.z;
                sm[b2 + (bq * 4 + 3) * 68 + brow] = bvreg0.w;
                sm[b2 + (bq * 4 + 16) * 68 + brow] = bvreg1.x;
                sm[b2 + (bq * 4 + 17) * 68 + brow] = bvreg1.y;
                sm[b2 + (bq * 4 + 18) * 68 + brow] = bvreg1.z;
                sm[b2 + (bq * 4 + 19) * 68 + brow] = bvreg1.w;
            }
            if (c == 1) {        // finalize Euclidean group (k 0..63 done)
#pragma unroll
                for (int i = 0; i < 4; i++) {
                    float an = sm[O_AN + ty * 4 + i];
#pragma unroll
                    for (int j = 0; j < 4; j++) {
                        float bn = sm[O_BN + tx * 4 + j];
                        s_[i][j] = cE * fast_sqrt(fmaxf(an + bn - 2.f * acc[i][j], 1e-12f));
                        acc[i][j] = 0.f;
                    }
                }
            }
            if (c == 3) {        // finalize spherical group (k 64..127 done)
#pragma unroll
                for (int i = 0; i < 4; i++)
#pragma unroll
                    for (int j = 0; j < 4; j++) {
                        float x = fminf(fmaxf(acc[i][j], -1.f + 1e-6f), 1.f - 1e-6f);
                        float ax = fabsf(x);
                        float poly = fmaf(ax, fmaf(ax, fmaf(ax, -0.0187293f, 0.0742610f), -0.2121144f), 1.5707288f);
                        float rr = fast_sqrt(1.f - ax) * poly;
                        float dS = (x >= 0.f) ? rr : (3.14159265358979f - rr);
                        s_[i][j] += cS * dS;
                        acc[i][j] = 0.f;
                    }
            }
            if (c == 4) {        // finalize hyperbolic group + temperature
#pragma unroll
                for (int i = 0; i < 4; i++) {
                    float un = sm[O_UN + ty * 4 + i];
                    float one_m_un = 1.f - un;
#pragma unroll
                    for (int j = 0; j < 4; j++) {
                        float vn = sm[O_VN + tx * 4 + j];
                        float dns = fmaxf(un + vn - 2.f * acc[i][j], 0.f);
                        float denom = one_m_un * (1.f - vn) + 1e-8f;
                        float t = fmaxf(2.f * dns * fast_rcp(denom), 1e-6f);
                        float sh = fast_sqrt(t * (t + 2.f));
                        float dHp = __logf(1.f + t + sh);
                        s_[i][j] = negInvT * (s_[i][j] + cH * dHp);
                    }
                }
            }
            if (c < 4) __syncthreads();
        }

        // prefetch V tile into registers (hidden behind softmax math)
        float4 vr[4];
#pragma unroll
        for (int t = 0; t < 4; t++) {
            int idx = tid + 256 * t;
            int c = idx >> 4, dq = idx & 15;
            vr[t] = *(const float4*)(Vb + (size_t)(col0 + c) * DH + dq * 4);
        }

        // online softmax update + P to smem
#pragma unroll
        for (int i = 0; i < 4; i++) {
            float rm = fmaxf(fmaxf(s_[i][0], s_[i][1]), fmaxf(s_[i][2], s_[i][3]));
#pragma unroll
            for (int o = 1; o < 16; o <<= 1) rm = fmaxf(rm, __shfl_xor_sync(0xffffffffu, rm, o));
            float mn = fmaxf(m_[i], rm);
            float sc = __expf(m_[i] - mn);
            float p0 = __expf(s_[i][0] - mn);
            float p1 = __expf(s_[i][1] - mn);
            float p2 = __expf(s_[i][2] - mn);
            float p3 = __expf(s_[i][3] - mn);
            float rs = (p0 + p1) + (p2 + p3);
#pragma unroll
            for (int o = 1; o < 16; o <<= 1) rs += __shfl_xor_sync(0xffffffffu, rs, o);
            l_[i] = l_[i] * sc + rs;
            m_[i] = mn;
            accO[i][0] *= sc; accO[i][1] *= sc; accO[i][2] *= sc; accO[i][3] *= sc;
            *(float4*)&sm[O_PS + (ty * 4 + i) * 68 + tx * 4] = make_float4(p0, p1, p2, p3);
        }
#pragma unroll
        for (int t = 0; t < 4; t++) {
            int idx = tid + 256 * t;
            int c = idx >> 4, dq = idx & 15;
            *(float4*)&sm[O_VS + c * 68 + dq * 4] = vr[t];
        }
        __syncthreads();

        // P @ V accumulation
#pragma unroll
        for (int c4 = 0; c4 < 16; c4++) {
            float4 pa0 = *(const float4*)&sm[O_PS + (ty * 4 + 0) * 68 + c4 * 4];
            float4 pa1 = *(const float4*)&sm[O_PS + (ty * 4 + 1) * 68 + c4 * 4];
            float4 pa2 = *(const float4*)&sm[O_PS + (ty * 4 + 2) * 68 + c4 * 4];
            float4 pa3 = *(const float4*)&sm[O_PS + (ty * 4 + 3) * 68 + c4 * 4];
            float4 vb0 = *(const float4*)&sm[O_VS + (c4 * 4 + 0) * 68 + tx * 4];
            float4 vb1 = *(const float4*)&sm[O_VS + (c4 * 4 + 1) * 68 + tx * 4];
            float4 vb2 = *(const float4*)&sm[O_VS + (c4 * 4 + 2) * 68 + tx * 4];
            float4 vb3 = *(const float4*)&sm[O_VS + (c4 * 4 + 3) * 68 + tx * 4];
            G2STEP(x, vb0)
            G2STEP(y, vb1)
            G2STEP(z, vb2)
            G2STEP(w, vb3)
        }
        __syncthreads();
    }

    // normalize + write O
    int b = bh / Hh, h = bh % Hh;
#pragma unroll
    for (int i = 0; i < 4; i++) {
        float inv = fast_rcp(l_[i]);
        float4 o = make_float4(accO[i][0] * inv, accO[i][1] * inv,
                               accO[i][2] * inv, accO[i][3] * inv);
        *(float4*)&g_O[((size_t)(b * Nn + row0 + ty * 4 + i)) * INNER + h * DH + tx * 4] = o;
    }
}

// ============================================================
// K6: final projection. 128x128 tile, 8x8 micro (R9 version, ~94% of floor).
// ============================================================
__global__ __launch_bounds__(256) void k_proj(const float* __restrict__ wp,
                                              const float* __restrict__ bp,
                                              float* __restrict__ out) {
    __shared__ float As[2][16][LDA];
    __shared__ float Bs[2][16][LDA];
    int tid = threadIdx.x;
    int ty = tid >> 4, tx = tid & 15;
    int srow = tid >> 1, sq = (tid & 1) * 2;
    const float* Ap = g_O + ((size_t)(blockIdx.y * 128) + srow) * INNER + sq * 4;
    const float* Bp = wp + ((size_t)(blockIdx.x * 128) + srow) * INNER + sq * 4;
    u64 acc2[8][4] = {};
    float4 a0v, a1v, b0v, b1v;

#define P_LDG(KT) \
    a0v = *(const float4*)(Ap + (KT) * 16);     a1v = *(const float4*)(Ap + (KT) * 16 + 4); \
    b0v = *(const float4*)(Bp + (KT) * 16);     b1v = *(const float4*)(Bp + (KT) * 16 + 4);
#define P_STS(BUF) \
    As[BUF][sq*4+0][srow]=a0v.x; As[BUF][sq*4+1][srow]=a0v.y; As[BUF][sq*4+2][srow]=a0v.z; As[BUF][sq*4+3][srow]=a0v.w; \
    As[BUF][sq*4+4][srow]=a1v.x; As[BUF][sq*4+5][srow]=a1v.y; As[BUF][sq*4+6][srow]=a1v.z; As[BUF][sq*4+7][srow]=a1v.w; \
    Bs[BUF][sq*4+0][srow]=b0v.x; Bs[BUF][sq*4+1][srow]=b0v.y; Bs[BUF][sq*4+2][srow]=b0v.z; Bs[BUF][sq*4+3][srow]=b0v.w; \
    Bs[BUF][sq*4+4][srow]=b1v.x; Bs[BUF][sq*4+5][srow]=b1v.y; Bs[BUF][sq*4+6][srow]=b1v.z; Bs[BUF][sq*4+7][srow]=b1v.w;
#define P_COMP(BUF) \
    _Pragma("unroll") \
    for (int kk = 0; kk < 16; kk++) { \
        float4 a0 = *(const float4*)&As[BUF][kk][ty * 8]; \
        float4 a1 = *(const float4*)&As[BUF][kk][ty * 8 + 4]; \
        float4 b0 = *(const float4*)&Bs[BUF][kk][tx * 8]; \
        float4 b1 = *(const float4*)&Bs[BUF][kk][tx * 8 + 4]; \
        MICRO8X8(acc2, a0, a1, b0, b1) \
    }

    P_LDG(0) P_STS(0)
    __syncthreads();
    for (int kt = 0; kt < 32; kt += 2) {
        if (kt + 1 < 32) { P_LDG(kt + 1) }
        P_COMP(0)
        if (kt + 1 < 32) { P_STS(1) }
        __syncthreads();
        if (kt + 1 < 32) {
            if (kt + 2 < 32) { P_LDG(kt + 2) }
            P_COMP(1)
            if (kt + 2 < 32) { P_STS(0) }
            __syncthreads();
        }
    }

    int m0 = blockIdx.y * 128 + ty * 8;
    int n0 = blockIdx.x * 128 + tx * 8;
    float4 bias0 = *(const float4*)&bp[n0];
    float4 bias1 = *(const float4*)&bp[n0 + 4];
#pragma unroll
    for (int i = 0; i < 8; i++) {
        float4 o0, o1;
        unpack2(acc2[i][0], o0.x, o0.y); unpack2(acc2[i][1], o0.z, o0.w);
        unpack2(acc2[i][2], o1.x, o1.y); unpack2(acc2[i][3], o1.z, o1.w);
        o0.x += bias0.x; o0.y += bias0.y; o0.z += bias0.z; o0.w += bias0.w;
        o1.x += bias1.x; o1.y += bias1.y; o1.z += bias1.z; o1.w += bias1.w;
        *(float4*)&out[(size_t)(m0 + i) * Cc + n0] = o0;
        *(float4*)&out[(size_t)(m0 + i) * Cc + n0 + 4] = o1;
    }
}

extern "C" void kernel_launch(void* const* d_in, const int* in_sizes, int n_in,
                              void* d_out, int out_size) {
    const float* x      = (const float*)d_in[0];
    const float* w_qkv  = (const float*)d_in[1];
    const float* w_proj = (const float*)d_in[2];
    const float* b_proj = (const float*)d_in[3];
    const float* w_e    = (const float*)d_in[4];
    const float* b_e    = (const float*)d_in[5];
    const float* w_s    = (const float*)d_in[6];
    const float* b_s    = (const float*)d_in[7];
    const float* w_h    = (const float*)d_in[8];
    const float* b_h    = (const float*)d_in[9];
    const float* alpha  = (const float*)d_in[10];
    const float* beta   = (const float*)d_in[11];
    const float* gamma  = (const float*)d_in[12];
    const float* temp   = (const float*)d_in[13];
    float* out = (float*)d_out;

    cudaFuncSetAttribute(k_attn, cudaFuncAttributeMaxDynamicSharedMemorySize, ATT_SMEM_BYTES);

    k_qkv<<<dim3(12, 32), 256>>>(x, w_qkv);
    k_embed<<<dim3(BH * Nn / 4, 2), 256>>>(w_e, b_e, w_s, b_s, w_h, b_h);
    k_attn<<<dim3(16, BH), 256, ATT_SMEM_BYTES>>>(alpha, beta, gamma, temp);
    k_proj<<<dim3(4, 32), 256>>>(w_proj, b_proj, out);
}

// round 12
// speedup vs baseline: 1.0269x; 1.0206x over previous
#include <cuda_runtime.h>
#include <cuda_bf16.h>
#include <math.h>
#include <stdint.h>

#define Bsz 4
#define Nn 1024
#define Cc 512
#define Hh 8
#define DH 64
#define BH 32
#define INNER 512
#define Ff 160   // 64 (E) + 64 (S) + 32 (H)
#define LDA 132  // smem stride for 128-wide tiles
#define NPART 4  // split-k parts (4 k-tiles each)

typedef unsigned long long u64;

// ---- scratch (static device allocations; no runtime alloc) ----
__device__ float g_Q[BH * Nn * DH];
__device__ float g_K[BH * Nn * DH];
__device__ float g_V[BH * Nn * DH];
__device__ float g_FQ[BH * Nn * Ff];
__device__ float g_FK[BH * Nn * Ff];
__device__ float g_QA[BH * Nn];
__device__ float g_QU[BH * Nn];
__device__ float g_KB[BH * Nn];
__device__ float g_KV[BH * Nn];
__device__ float g_O[Bsz * Nn * INNER];
// split-k partials
__device__ float g_Pm[NPART][BH * Nn];
__device__ float g_Pl[NPART][BH * Nn];
__device__ float g_Po[NPART][(size_t)BH * Nn * DH];

__device__ __forceinline__ float softplusf(float x) {
    return (x > 20.f) ? x : log1pf(expf(x));
}
__device__ __forceinline__ float fast_sqrt(float x) {
    float r; asm("sqrt.approx.f32 %0, %1;" : "=f"(r) : "f"(x)); return r;
}
__device__ __forceinline__ float fast_rcp(float x) {
    float r; asm("rcp.approx.f32 %0, %1;" : "=f"(r) : "f"(x)); return r;
}

// ---- packed f32x2 FMA ----
__device__ __forceinline__ void fma2(u64& d, u64 a, u64 b) {
    asm("fma.rn.f32x2 %0, %1, %2, %0;" : "+l"(d) : "l"(a), "l"(b));
}
__device__ __forceinline__ u64 pack2(float lo, float hi) {
    u64 r; asm("mov.b64 %0, {%1, %2};" : "=l"(r) : "f"(lo), "f"(hi)); return r;
}
__device__ __forceinline__ void unpack2(u64 v, float& lo, float& hi) {
    asm("mov.b64 {%0, %1}, %2;" : "=f"(lo), "=f"(hi) : "l"(v));
}

#define MICRO8X8(ACC2, a0, a1, b0, b1) {                                      \
    u64 q0 = pack2(b0.x, b0.y), q1 = pack2(b0.z, b0.w);                       \
    u64 q2 = pack2(b1.x, b1.y), q3 = pack2(b1.z, b1.w);                       \
    u64 ar;                                                                   \
    ar = pack2(a0.x, a0.x); fma2(ACC2[0][0],ar,q0); fma2(ACC2[0][1],ar,q1); fma2(ACC2[0][2],ar,q2); fma2(ACC2[0][3],ar,q3); \
    ar = pack2(a0.y, a0.y); fma2(ACC2[1][0],ar,q0); fma2(ACC2[1][1],ar,q1); fma2(ACC2[1][2],ar,q2); fma2(ACC2[1][3],ar,q3); \
    ar = pack2(a0.z, a0.z); fma2(ACC2[2][0],ar,q0); fma2(ACC2[2][1],ar,q1); fma2(ACC2[2][2],ar,q2); fma2(ACC2[2][3],ar,q3); \
    ar = pack2(a0.w, a0.w); fma2(ACC2[3][0],ar,q0); fma2(ACC2[3][1],ar,q1); fma2(ACC2[3][2],ar,q2); fma2(ACC2[3][3],ar,q3); \
    ar = pack2(a1.x, a1.x); fma2(ACC2[4][0],ar,q0); fma2(ACC2[4][1],ar,q1); fma2(ACC2[4][2],ar,q2); fma2(ACC2[4][3],ar,q3); \
    ar = pack2(a1.y, a1.y); fma2(ACC2[5][0],ar,q0); fma2(ACC2[5][1],ar,q1); fma2(ACC2[5][2],ar,q2); fma2(ACC2[5][3],ar,q3); \
    ar = pack2(a1.z, a1.z); fma2(ACC2[6][0],ar,q0); fma2(ACC2[6][1],ar,q1); fma2(ACC2[6][2],ar,q2); fma2(ACC2[6][3],ar,q3); \
    ar = pack2(a1.w, a1.w); fma2(ACC2[7][0],ar,q0); fma2(ACC2[7][1],ar,q1); fma2(ACC2[7][2],ar,q2); fma2(ACC2[7][3],ar,q3); \
}

// ============================================================
// K1: qkv = x @ w_qkv^T -> per-head Q/K/V. 128x128 tile, 8x8 micro.
// ============================================================
__global__ __launch_bounds__(256) void k_qkv(const float* __restrict__ x,
                                             const float* __restrict__ w) {
    __shared__ float As[2][16][LDA];
    __shared__ float Bs[2][16][LDA];
    int tid = threadIdx.x;
    int ty = tid >> 4, tx = tid & 15;
    int srow = tid >> 1, sq = (tid & 1) * 2;
    const float* Ap = x + ((size_t)(blockIdx.y * 128) + srow) * Cc + sq * 4;
    const float* Bp = w + ((size_t)(blockIdx.x * 128) + srow) * Cc + sq * 4;
    u64 acc2[8][4] = {};
    float4 a0v, a1v, b0v, b1v;

#define Q_LDG(KT) \
    a0v = *(const float4*)(Ap + (KT) * 16);     a1v = *(const float4*)(Ap + (KT) * 16 + 4); \
    b0v = *(const float4*)(Bp + (KT) * 16);     b1v = *(const float4*)(Bp + (KT) * 16 + 4);
#define Q_STS(BUF) \
    As[BUF][sq*4+0][srow]=a0v.x; As[BUF][sq*4+1][srow]=a0v.y; As[BUF][sq*4+2][srow]=a0v.z; As[BUF][sq*4+3][srow]=a0v.w; \
    As[BUF][sq*4+4][srow]=a1v.x; As[BUF][sq*4+5][srow]=a1v.y; As[BUF][sq*4+6][srow]=a1v.z; As[BUF][sq*4+7][srow]=a1v.w; \
    Bs[BUF][sq*4+0][srow]=b0v.x; Bs[BUF][sq*4+1][srow]=b0v.y; Bs[BUF][sq*4+2][srow]=b0v.z; Bs[BUF][sq*4+3][srow]=b0v.w; \
    Bs[BUF][sq*4+4][srow]=b1v.x; Bs[BUF][sq*4+5][srow]=b1v.y; Bs[BUF][sq*4+6][srow]=b1v.z; Bs[BUF][sq*4+7][srow]=b1v.w;
#define Q_COMP(BUF) \
    _Pragma("unroll") \
    for (int kk = 0; kk < 16; kk++) { \
        float4 a0 = *(const float4*)&As[BUF][kk][ty * 8]; \
        float4 a1 = *(const float4*)&As[BUF][kk][ty * 8 + 4]; \
        float4 b0 = *(const float4*)&Bs[BUF][kk][tx * 8]; \
        float4 b1 = *(const float4*)&Bs[BUF][kk][tx * 8 + 4]; \
        MICRO8X8(acc2, a0, a1, b0, b1) \
    }

    Q_LDG(0) Q_STS(0)
    __syncthreads();
    for (int kt = 0; kt < 32; kt += 2) {
        if (kt + 1 < 32) { Q_LDG(kt + 1) }
        Q_COMP(0)
        if (kt + 1 < 32) { Q_STS(1) }
        __syncthreads();
        if (kt + 1 < 32) {
            if (kt + 2 < 32) { Q_LDG(kt + 2) }
            Q_COMP(1)
            if (kt + 2 < 32) { Q_STS(0) }
            __syncthreads();
        }
    }

    float acc[8][8];
#pragma unroll
    for (int i = 0; i < 8; i++)
#pragma unroll
        for (int p = 0; p < 4; p++) unpack2(acc2[i][p], acc[i][2 * p], acc[i][2 * p + 1]);

    int m0 = blockIdx.y * 128 + ty * 8;
    int n0 = blockIdx.x * 128 + tx * 8;
#pragma unroll
    for (int i = 0; i < 8; i++) {
        int m = m0 + i;
        int b = m / Nn, n = m % Nn;
#pragma unroll
        for (int j = 0; j < 8; j++) {
            int jc = n0 + j;
            int part = jc / INNER, r = jc % INNER;
            int h = r / DH, d = r % DH;
            float* dst = (part == 0) ? g_Q : ((part == 1) ? g_K : g_V);
            dst[((size_t)(b * Hh + h) * Nn + n) * DH + d] = acc[i][j];
        }
    }
}

// ============================================================
// K2: per-token metric embeddings (unchanged)
// ============================================================
__global__ __launch_bounds__(256) void k_embed(const float* __restrict__ we, const float* __restrict__ be,
                                               const float* __restrict__ ws, const float* __restrict__ bs,
                                               const float* __restrict__ wh, const float* __restrict__ bhh) {
    __shared__ float W[Ff][65];
    __shared__ float bias[Ff];
    __shared__ float qr[4][64];
    __shared__ float raw[4][Ff];
    int tid = threadIdx.x;
    for (int i = tid; i < 64 * 64; i += 256) { W[i / 64][i % 64] = we[i]; W[64 + i / 64][i % 64] = ws[i]; }
    for (int i = tid; i < 32 * 64; i += 256) W[128 + i / 64][i % 64] = wh[i];
    for (int i = tid; i < Ff; i += 256) bias[i] = (i < 64) ? be[i] : ((i < 128) ? bs[i - 64] : bhh[i - 128]);
    const float* src = (blockIdx.y == 0) ? g_Q : g_K;
    int tok0 = blockIdx.x * 4;
    for (int i = tid; i < 4 * 64; i += 256) qr[i / 64][i % 64] = src[(size_t)(tok0 + i / 64) * 64 + (i % 64)];
    __syncthreads();
    for (int i = tid; i < 4 * Ff; i += 256) {
        int tt = i / Ff, j = i % Ff;
        float s = bias[j];
#pragma unroll 8
        for (int c = 0; c < 64; c++) s += qr[tt][c] * W[j][c];
        raw[tt][j] = s;
    }
    __syncthreads();
    int w = tid >> 5, lane = tid & 31;
    if (w < 4) {
        int tt = w;
        float an = 0.f, sn = 0.f, un = 0.f;
        for (int j = lane; j < 64; j += 32) { float v = raw[tt][j]; an += v * v; }
        for (int j = 64 + lane; j < 128; j += 32) { float v = raw[tt][j]; sn += v * v; }
        {
            int j = 128 + lane;
            float th = tanhf(raw[tt][j]);
            raw[tt][j] = th;
            un += th * th;
        }
#pragma unroll
        for (int o = 16; o; o >>= 1) {
            an += __shfl_xor_sync(0xffffffffu, an, o);
            sn += __shfl_xor_sync(0xffffffffu, sn, o);
            un += __shfl_xor_sync(0xffffffffu, un, o);
        }
        float inv = 1.f / fmaxf(sqrtf(sn), 1e-12f);
        __syncwarp();
        float* Fdst = (blockIdx.y == 0) ? g_FQ : g_FK;
        int tok = tok0 + tt;
        for (int j = lane; j < Ff; j += 32) {
            float v = raw[tt][j];
            if (j >= 64 && j < 128) v *= inv;
            Fdst[(size_t)tok * Ff + j] = v;
        }
        if (lane == 0) {
            if (blockIdx.y == 0) { g_QA[tok] = an; g_QU[tok] = un; }
            else                 { g_KB[tok] = an; g_KV[tok] = un; }
        }
    }
}

// ============================================================
// K3: FUSED attention, SPLIT-K over 4 parts (4 k-tiles each).
// Writes unnormalized partials (m, l, accO) per part.
// ============================================================
#define O_ARES 0        // 160 x 68
#define O_BS   10880    // 2 x 32 x 68
#define O_PS   15232    // 64 x 68
#define O_VS   19584    // 64 x 68
#define O_AN   23936
#define O_UN   24000
#define O_BN   24064
#define O_VN   24128
#define ATT_SMEM_BYTES (24192 * 4)   // 96768 B

#define FMA16(ACC, a, b) \
    ACC[0][0] += a.x * b.x; ACC[0][1] += a.x * b.y; ACC[0][2] += a.x * b.z; ACC[0][3] += a.x * b.w; \
    ACC[1][0] += a.y * b.x; ACC[1][1] += a.y * b.y; ACC[1][2] += a.y * b.z; ACC[1][3] += a.y * b.w; \
    ACC[2][0] += a.z * b.x; ACC[2][1] += a.z * b.y; ACC[2][2] += a.z * b.z; ACC[2][3] += a.z * b.w; \
    ACC[3][0] += a.w * b.x; ACC[3][1] += a.w * b.y; ACC[3][2] += a.w * b.z; ACC[3][3] += a.w * b.w;

#define G2STEP(E, VB) { \
    accO[0][0]+=pa0.E*VB.x; accO[0][1]+=pa0.E*VB.y; accO[0][2]+=pa0.E*VB.z; accO[0][3]+=pa0.E*VB.w; \
    accO[1][0]+=pa1.E*VB.x; accO[1][1]+=pa1.E*VB.y; accO[1][2]+=pa1.E*VB.z; accO[1][3]+=pa1.E*VB.w; \
    accO[2][0]+=pa2.E*VB.x; accO[2][1]+=pa2.E*VB.y; accO[2][2]+=pa2.E*VB.z; accO[2][3]+=pa2.E*VB.w; \
    accO[3][0]+=pa3.E*VB.x; accO[3][1]+=pa3.E*VB.y; accO[3][2]+=pa3.E*VB.z; accO[3][3]+=pa3.E*VB.w; }

__global__ __launch_bounds__(256, 2) void k_attn(const float* __restrict__ alpha,
                                                 const float* __restrict__ beta,
                                                 const float* __restrict__ gamma,
                                                 const float* __restrict__ temp) {
    extern __shared__ float sm[];
    int tid = threadIdx.x;
    int ty = tid >> 4, tx = tid & 15;
    int brow = tid >> 2, bq = tid & 3;
    int bh = blockIdx.y;
    int row0 = blockIdx.x * 64;
    int part = blockIdx.z;

    const float* FQb = g_FQ + ((size_t)bh * Nn + row0) * Ff;
    const float* FKb = g_FK + (size_t)bh * Nn * Ff;
    const float* Vb  = g_V + (size_t)bh * Nn * DH;

#pragma unroll
    for (int t = 0; t < 10; t++) {
        int idx = tid + 256 * t;
        int r = idx / 40, q4 = idx % 40;
        float4 v = *(const float4*)(FQb + (size_t)r * Ff + q4 * 4);
        sm[O_ARES + (q4 * 4 + 0) * 68 + r] = v.x;
        sm[O_ARES + (q4 * 4 + 1) * 68 + r] = v.y;
        sm[O_ARES + (q4 * 4 + 2) * 68 + r] = v.z;
        sm[O_ARES + (q4 * 4 + 3) * 68 + r] = v.w;
    }
    if (tid < 64) {
        sm[O_AN + tid] = g_QA[bh * Nn + row0 + tid];
        sm[O_UN + tid] = g_QU[bh * Nn + row0 + tid];
    }

    float cE = softplusf(alpha[0]);
    float cS = softplusf(beta[0]);
    float cH = softplusf(gamma[0]);
    float negInvT = -1.f / softplusf(temp[0]);

    float m_[4], l_[4], accO[4][4];
#pragma unroll
    for (int i = 0; i < 4; i++) {
        m_[i] = -1e30f; l_[i] = 0.f;
#pragma unroll
        for (int j = 0; j < 4; j++) accO[i][j] = 0.f;
    }
    __syncthreads();

    for (int kt = part * 4; kt < part * 4 + 4; kt++) {
        int col0 = kt * 64;
        const float* Bp = FKb + (size_t)(col0 + brow) * Ff + bq * 4;

        {
            float4 v0 = *(const float4*)(Bp);
            float4 v1 = *(const float4*)(Bp + 16);
            sm[O_BS + (bq * 4 + 0) * 68 + brow] = v0.x;
            sm[O_BS + (bq * 4 + 1) * 68 + brow] = v0.y;
            sm[O_BS + (bq * 4 + 2) * 68 + brow] = v0.z;
            sm[O_BS + (bq * 4 + 3) * 68 + brow] = v0.w;
            sm[O_BS + (bq * 4 + 16) * 68 + brow] = v1.x;
            sm[O_BS + (bq * 4 + 17) * 68 + brow] = v1.y;
            sm[O_BS + (bq * 4 + 18) * 68 + brow] = v1.z;
            sm[O_BS + (bq * 4 + 19) * 68 + brow] = v1.w;
        }
        if (tid < 64) {
            sm[O_BN + tid] = g_KB[bh * Nn + col0 + tid];
            sm[O_VN + tid] = g_KV[bh * Nn + col0 + tid];
        }
        __syncthreads();

        float acc[4][4] = {};
        float s_[4][4];
        float4 bvreg0, bvreg1;

#pragma unroll
        for (int c = 0; c < 5; c++) {
            if (c < 4) {
                bvreg0 = *(const float4*)(Bp + (c + 1) * 32);
                bvreg1 = *(const float4*)(Bp + (c + 1) * 32 + 16);
            }
            int bb = O_BS + (c & 1) * 2176;
#pragma unroll
            for (int kk = 0; kk < 32; kk++) {
                float4 a = *(const float4*)&sm[O_ARES + (c * 32 + kk) * 68 + ty * 4];
                float4 b = *(const float4*)&sm[bb + kk * 68 + tx * 4];
                FMA16(acc, a, b)
            }
            if (c < 4) {
                int b2 = O_BS + ((c + 1) & 1) * 2176;
                sm[b2 + (bq * 4 + 0) * 68 + brow] = bvreg0.x;
                sm[b2 + (bq * 4 + 1) * 68 + brow] = bvreg0.y;
                sm[b2 + (bq * 4 + 2) * 68 + brow] = bvreg0.z;
                sm[b2 + (bq * 4 + 3) * 68 + brow] = bvreg0.w;
                sm[b2 + (bq * 4 + 16) * 68 + brow] = bvreg1.x;
                sm[b2 + (bq * 4 + 17) * 68 + brow] = bvreg1.y;
                sm[b2 + (bq * 4 + 18) * 68 + brow] = bvreg1.z;
                sm[b2 + (bq * 4 + 19) * 68 + brow] = bvreg1.w;
            }
            if (c == 1) {
#pragma unroll
                for (int i = 0; i < 4; i++) {
                    float an = sm[O_AN + ty * 4 + i];
#pragma unroll
                    for (int j = 0; j < 4; j++) {
                        float bn = sm[O_BN + tx * 4 + j];
                        s_[i][j] = cE * fast_sqrt(fmaxf(an + bn - 2.f * acc[i][j], 1e-12f));
                        acc[i][j] = 0.f;
                    }
                }
            }
            if (c == 3) {
#pragma unroll
                for (int i = 0; i < 4; i++)
#pragma unroll
                    for (int j = 0; j < 4; j++) {
                        float x = fminf(fmaxf(acc[i][j], -1.f + 1e-6f), 1.f - 1e-6f);
                        float ax = fabsf(x);
                        float poly = fmaf(ax, fmaf(ax, fmaf(ax, -0.0187293f, 0.0742610f), -0.2121144f), 1.5707288f);
                        float rr = fast_sqrt(1.f - ax) * poly;
                        float dS = (x >= 0.f) ? rr : (3.14159265358979f - rr);
                        s_[i][j] += cS * dS;
                        acc[i][j] = 0.f;
                    }
            }
            if (c == 4) {
#pragma unroll
                for (int i = 0; i < 4; i++) {
                    float un = sm[O_UN + ty * 4 + i];
                    float one_m_un = 1.f - un;
#pragma unroll
                    for (int j = 0; j < 4; j++) {
                        float vn = sm[O_VN + tx * 4 + j];
                        float dns = fmaxf(un + vn - 2.f * acc[i][j], 0.f);
                        float denom = one_m_un * (1.f - vn) + 1e-8f;
                        float t = fmaxf(2.f * dns * fast_rcp(denom), 1e-6f);
                        float sh = fast_sqrt(t * (t + 2.f));
                        float dHp = __logf(1.f + t + sh);
                        s_[i][j] = negInvT * (s_[i][j] + cH * dHp);
                    }
                }
            }
            if (c < 4) __syncthreads();
        }

        float4 vr[4];
#pragma unroll
        for (int t = 0; t < 4; t++) {
            int idx = tid + 256 * t;
            int c = idx >> 4, dq = idx & 15;
            vr[t] = *(const float4*)(Vb + (size_t)(col0 + c) * DH + dq * 4);
        }

#pragma unroll
        for (int i = 0; i < 4; i++) {
            float rm = fmaxf(fmaxf(s_[i][0], s_[i][1]), fmaxf(s_[i][2], s_[i][3]));
#pragma unroll
            for (int o = 1; o < 16; o <<= 1) rm = fmaxf(rm, __shfl_xor_sync(0xffffffffu, rm, o));
            float mn = fmaxf(m_[i], rm);
            float sc = __expf(m_[i] - mn);
            float p0 = __expf(s_[i][0] - mn);
            float p1 = __expf(s_[i][1] - mn);
            float p2 = __expf(s_[i][2] - mn);
            float p3 = __expf(s_[i][3] - mn);
            float rs = (p0 + p1) + (p2 + p3);
#pragma unroll
            for (int o = 1; o < 16; o <<= 1) rs += __shfl_xor_sync(0xffffffffu, rs, o);
            l_[i] = l_[i] * sc + rs;
            m_[i] = mn;
            accO[i][0] *= sc; accO[i][1] *= sc; accO[i][2] *= sc; accO[i][3] *= sc;
            *(float4*)&sm[O_PS + (ty * 4 + i) * 68 + tx * 4] = make_float4(p0, p1, p2, p3);
        }
#pragma unroll
        for (int t = 0; t < 4; t++) {
            int idx = tid + 256 * t;
            int c = idx >> 4, dq = idx & 15;
            *(float4*)&sm[O_VS + c * 68 + dq * 4] = vr[t];
        }
        __syncthreads();

#pragma unroll
        for (int c4 = 0; c4 < 16; c4++) {
            float4 pa0 = *(const float4*)&sm[O_PS + (ty * 4 + 0) * 68 + c4 * 4];
            float4 pa1 = *(const float4*)&sm[O_PS + (ty * 4 + 1) * 68 + c4 * 4];
            float4 pa2 = *(const float4*)&sm[O_PS + (ty * 4 + 2) * 68 + c4 * 4];
            float4 pa3 = *(const float4*)&sm[O_PS + (ty * 4 + 3) * 68 + c4 * 4];
            float4 vb0 = *(const float4*)&sm[O_VS + (c4 * 4 + 0) * 68 + tx * 4];
            float4 vb1 = *(const float4*)&sm[O_VS + (c4 * 4 + 1) * 68 + tx * 4];
            float4 vb2 = *(const float4*)&sm[O_VS + (c4 * 4 + 2) * 68 + tx * 4];
            float4 vb3 = *(const float4*)&sm[O_VS + (c4 * 4 + 3) * 68 + tx * 4];
            G2STEP(x, vb0)
            G2STEP(y, vb1)
            G2STEP(z, vb2)
            G2STEP(w, vb3)
        }
        __syncthreads();
    }

    // write unnormalized partials
#pragma unroll
    for (int i = 0; i < 4; i++) {
        int rowIdx = bh * Nn + row0 + ty * 4 + i;
        *(float4*)&g_Po[part][(size_t)rowIdx * DH + tx * 4] =
            make_float4(accO[i][0], accO[i][1], accO[i][2], accO[i][3]);
        if (tx == 0) {
            g_Pm[part][rowIdx] = m_[i];
            g_Pl[part][rowIdx] = l_[i];
        }
    }
}

// ============================================================
// K4: merge split-k partials -> g_O (b, n, h*64+d layout)
// ============================================================
__global__ __launch_bounds__(256) void k_merge() {
    int tid = threadIdx.x;
    int rowIdx = blockIdx.x * 4 + (tid >> 6);
    int d = tid & 63;
    float m0 = g_Pm[0][rowIdx], m1 = g_Pm[1][rowIdx];
    float m2 = g_Pm[2][rowIdx], m3 = g_Pm[3][rowIdx];
    float M = fmaxf(fmaxf(m0, m1), fmaxf(m2, m3));
    float w0 = __expf(m0 - M), w1 = __expf(m1 - M);
    float w2 = __expf(m2 - M), w3 = __expf(m3 - M);
    float L = g_Pl[0][rowIdx] * w0 + g_Pl[1][rowIdx] * w1
            + g_Pl[2][rowIdx] * w2 + g_Pl[3][rowIdx] * w3;
    size_t base = (size_t)rowIdx * DH + d;
    float val = g_Po[0][base] * w0 + g_Po[1][base] * w1
              + g_Po[2][base] * w2 + g_Po[3][base] * w3;
    int bh = rowIdx / Nn, n = rowIdx % Nn;
    int b = bh / Hh, h = bh % Hh;
    g_O[((size_t)(b * Nn + n)) * INNER + h * DH + d] = val * fast_rcp(L);
}

// ============================================================
// K6: final projection. 128x128 tile, 8x8 micro.
// ============================================================
__global__ __launch_bounds__(256) void k_proj(const float* __restrict__ wp,
                                              const float* __restrict__ bp,
                                              float* __restrict__ out) {
    __shared__ float As[2][16][LDA];
    __shared__ float Bs[2][16][LDA];
    int tid = threadIdx.x;
    int ty = tid >> 4, tx = tid & 15;
    int srow = tid >> 1, sq = (tid & 1) * 2;
    const float* Ap = g_O + ((size_t)(blockIdx.y * 128) + srow) * INNER + sq * 4;
    const float* Bp = wp + ((size_t)(blockIdx.x * 128) + srow) * INNER + sq * 4;
    u64 acc2[8][4] = {};
    float4 a0v, a1v, b0v, b1v;

#define P_LDG(KT) \
    a0v = *(const float4*)(Ap + (KT) * 16);     a1v = *(const float4*)(Ap + (KT) * 16 + 4); \
    b0v = *(const float4*)(Bp + (KT) * 16);     b1v = *(const float4*)(Bp + (KT) * 16 + 4);
#define P_STS(BUF) \
    As[BUF][sq*4+0][srow]=a0v.x; As[BUF][sq*4+1][srow]=a0v.y; As[BUF][sq*4+2][srow]=a0v.z; As[BUF][sq*4+3][srow]=a0v.w; \
    As[BUF][sq*4+4][srow]=a1v.x; As[BUF][sq*4+5][srow]=a1v.y; As[BUF][sq*4+6][srow]=a1v.z; As[BUF][sq*4+7][srow]=a1v.w; \
    Bs[BUF][sq*4+0][srow]=b0v.x; Bs[BUF][sq*4+1][srow]=b0v.y; Bs[BUF][sq*4+2][srow]=b0v.z; Bs[BUF][sq*4+3][srow]=b0v.w; \
    Bs[BUF][sq*4+4][srow]=b1v.x; Bs[BUF][sq*4+5][srow]=b1v.y; Bs[BUF][sq*4+6][srow]=b1v.z; Bs[BUF][sq*4+7][srow]=b1v.w;
#define P_COMP(BUF) \
    _Pragma("unroll") \
    for (int kk = 0; kk < 16; kk++) { \
        float4 a0 = *(const float4*)&As[BUF][kk][ty * 8]; \
        float4 a1 = *(const float4*)&As[BUF][kk][ty * 8 + 4]; \
        float4 b0 = *(const float4*)&Bs[BUF][kk][tx * 8]; \
        float4 b1 = *(const float4*)&Bs[BUF][kk][tx * 8 + 4]; \
        MICRO8X8(acc2, a0, a1, b0, b1) \
    }

    P_LDG(0) P_STS(0)
    __syncthreads();
    for (int kt = 0; kt < 32; kt += 2) {
        if (kt + 1 < 32) { P_LDG(kt + 1) }
        P_COMP(0)
        if (kt + 1 < 32) { P_STS(1) }
        __syncthreads();
        if (kt + 1 < 32) {
            if (kt + 2 < 32) { P_LDG(kt + 2) }
            P_COMP(1)
            if (kt + 2 < 32) { P_STS(0) }
            __syncthreads();
        }
    }

    int m0 = blockIdx.y * 128 + ty * 8;
    int n0 = blockIdx.x * 128 + tx * 8;
    float4 bias0 = *(const float4*)&bp[n0];
    float4 bias1 = *(const float4*)&bp[n0 + 4];
#pragma unroll
    for (int i = 0; i < 8; i++) {
        float4 o0, o1;
        unpack2(acc2[i][0], o0.x, o0.y); unpack2(acc2[i][1], o0.z, o0.w);
        unpack2(acc2[i][2], o1.x, o1.y); unpack2(acc2[i][3], o1.z, o1.w);
        o0.x += bias0.x; o0.y += bias0.y; o0.z += bias0.z; o0.w += bias0.w;
        o1.x += bias1.x; o1.y += bias1.y; o1.z += bias1.z; o1.w += bias1.w;
        *(float4*)&out[(size_t)(m0 + i) * Cc + n0] = o0;
        *(float4*)&out[(size_t)(m0 + i) * Cc + n0 + 4] = o1;
    }
}

extern "C" void kernel_launch(void* const* d_in, const int* in_sizes, int n_in,
                              void* d_out, int out_size) {
    const float* x      = (const float*)d_in[0];
    const float* w_qkv  = (const float*)d_in[1];
    const float* w_proj = (const float*)d_in[2];
    const float* b_proj = (const float*)d_in[3];
    const float* w_e    = (const float*)d_in[4];
    const float* b_e    = (const float*)d_in[5];
    const float* w_s    = (const float*)d_in[6];
    const float* b_s    = (const float*)d_in[7];
    const float* w_h    = (const float*)d_in[8];
    const float* b_h    = (const float*)d_in[9];
    const float* alpha  = (const float*)d_in[10];
    const float* beta   = (const float*)d_in[11];
    const float* gamma  = (const float*)d_in[12];
    const float* temp   = (const float*)d_in[13];
    float* out = (float*)d_out;

    cudaFuncSetAttribute(k_attn, cudaFuncAttributeMaxDynamicSharedMemorySize, ATT_SMEM_BYTES);

    k_qkv<<<dim3(12, 32), 256>>>(x, w_qkv);
    k_embed<<<dim3(BH * Nn / 4, 2), 256>>>(w_e, b_e, w_s, b_s, w_h, b_h);
    k_attn<<<dim3(16, BH, NPART), 256, ATT_SMEM_BYTES>>>(alpha, beta, gamma, temp);
    k_merge<<<BH * Nn / 4, 256>>>();
    k_proj<<<dim3(4, 32), 256>>>(w_proj, b_proj, out);
}

// round 13
// speedup vs baseline: 1.0490x; 1.0215x over previous
#include <cuda_runtime.h>
#include <cuda_bf16.h>
#include <math.h>
#include <stdint.h>

#define Bsz 4
#define Nn 1024
#define Cc 512
#define Hh 8
#define DH 64
#define BH 32
#define INNER 512
#define Ff 160   // 64 (E) + 64 (S) + 32 (H)
#define LDA 132  // smem stride for 128-wide tiles
#define NPART 4  // split-k parts (4 k-tiles each)

typedef unsigned long long u64;

// ---- scratch (static device allocations; no runtime alloc) ----
__device__ float g_Q[BH * Nn * DH];
__device__ float g_K[BH * Nn * DH];
__device__ float g_V[BH * Nn * DH];
__device__ float g_FQ[BH * Nn * Ff];
__device__ float g_FK[BH * Nn * Ff];
__device__ float g_QA[BH * Nn];
__device__ float g_QU[BH * Nn];
__device__ float g_KB[BH * Nn];
__device__ float g_KV[BH * Nn];
__device__ float g_O[Bsz * Nn * INNER];
// split-k partials (unnormalized; scores <= 0 so no max-tracking needed)
__device__ float g_Pl[NPART][BH * Nn];
__device__ float g_Po[NPART][(size_t)BH * Nn * DH];

__device__ __forceinline__ float softplusf(float x) {
    return (x > 20.f) ? x : log1pf(expf(x));
}
__device__ __forceinline__ float fast_sqrt(float x) {
    float r; asm("sqrt.approx.f32 %0, %1;" : "=f"(r) : "f"(x)); return r;
}
__device__ __forceinline__ float fast_rcp(float x) {
    float r; asm("rcp.approx.f32 %0, %1;" : "=f"(r) : "f"(x)); return r;
}

// ---- packed f32x2 FMA ----
__device__ __forceinline__ void fma2(u64& d, u64 a, u64 b) {
    asm("fma.rn.f32x2 %0, %1, %2, %0;" : "+l"(d) : "l"(a), "l"(b));
}
__device__ __forceinline__ u64 pack2(float lo, float hi) {
    u64 r; asm("mov.b64 %0, {%1, %2};" : "=l"(r) : "f"(lo), "f"(hi)); return r;
}
__device__ __forceinline__ void unpack2(u64 v, float& lo, float& hi) {
    asm("mov.b64 {%0, %1}, %2;" : "=f"(lo), "=f"(hi) : "l"(v));
}

#define MICRO8X8(ACC2, a0, a1, b0, b1) {                                      \
    u64 q0 = pack2(b0.x, b0.y), q1 = pack2(b0.z, b0.w);                       \
    u64 q2 = pack2(b1.x, b1.y), q3 = pack2(b1.z, b1.w);                       \
    u64 ar;                                                                   \
    ar = pack2(a0.x, a0.x); fma2(ACC2[0][0],ar,q0); fma2(ACC2[0][1],ar,q1); fma2(ACC2[0][2],ar,q2); fma2(ACC2[0][3],ar,q3); \
    ar = pack2(a0.y, a0.y); fma2(ACC2[1][0],ar,q0); fma2(ACC2[1][1],ar,q1); fma2(ACC2[1][2],ar,q2); fma2(ACC2[1][3],ar,q3); \
    ar = pack2(a0.z, a0.z); fma2(ACC2[2][0],ar,q0); fma2(ACC2[2][1],ar,q1); fma2(ACC2[2][2],ar,q2); fma2(ACC2[2][3],ar,q3); \
    ar = pack2(a0.w, a0.w); fma2(ACC2[3][0],ar,q0); fma2(ACC2[3][1],ar,q1); fma2(ACC2[3][2],ar,q2); fma2(ACC2[3][3],ar,q3); \
    ar = pack2(a1.x, a1.x); fma2(ACC2[4][0],ar,q0); fma2(ACC2[4][1],ar,q1); fma2(ACC2[4][2],ar,q2); fma2(ACC2[4][3],ar,q3); \
    ar = pack2(a1.y, a1.y); fma2(ACC2[5][0],ar,q0); fma2(ACC2[5][1],ar,q1); fma2(ACC2[5][2],ar,q2); fma2(ACC2[5][3],ar,q3); \
    ar = pack2(a1.z, a1.z); fma2(ACC2[6][0],ar,q0); fma2(ACC2[6][1],ar,q1); fma2(ACC2[6][2],ar,q2); fma2(ACC2[6][3],ar,q3); \
    ar = pack2(a1.w, a1.w); fma2(ACC2[7][0],ar,q0); fma2(ACC2[7][1],ar,q1); fma2(ACC2[7][2],ar,q2); fma2(ACC2[7][3],ar,q3); \
}

// ============================================================
// K1: qkv = x @ w_qkv^T -> per-head Q/K/V. 128x128 tile, 8x8 micro.
// ============================================================
__global__ __launch_bounds__(256) void k_qkv(const float* __restrict__ x,
                                             const float* __restrict__ w) {
    __shared__ float As[2][16][LDA];
    __shared__ float Bs[2][16][LDA];
    int tid = threadIdx.x;
    int ty = tid >> 4, tx = tid & 15;
    int srow = tid >> 1, sq = (tid & 1) * 2;
    const float* Ap = x + ((size_t)(blockIdx.y * 128) + srow) * Cc + sq * 4;
    const float* Bp = w + ((size_t)(blockIdx.x * 128) + srow) * Cc + sq * 4;
    u64 acc2[8][4] = {};
    float4 a0v, a1v, b0v, b1v;

#define Q_LDG(KT) \
    a0v = *(const float4*)(Ap + (KT) * 16);     a1v = *(const float4*)(Ap + (KT) * 16 + 4); \
    b0v = *(const float4*)(Bp + (KT) * 16);     b1v = *(const float4*)(Bp + (KT) * 16 + 4);
#define Q_STS(BUF) \
    As[BUF][sq*4+0][srow]=a0v.x; As[BUF][sq*4+1][srow]=a0v.y; As[BUF][sq*4+2][srow]=a0v.z; As[BUF][sq*4+3][srow]=a0v.w; \
    As[BUF][sq*4+4][srow]=a1v.x; As[BUF][sq*4+5][srow]=a1v.y; As[BUF][sq*4+6][srow]=a1v.z; As[BUF][sq*4+7][srow]=a1v.w; \
    Bs[BUF][sq*4+0][srow]=b0v.x; Bs[BUF][sq*4+1][srow]=b0v.y; Bs[BUF][sq*4+2][srow]=b0v.z; Bs[BUF][sq*4+3][srow]=b0v.w; \
    Bs[BUF][sq*4+4][srow]=b1v.x; Bs[BUF][sq*4+5][srow]=b1v.y; Bs[BUF][sq*4+6][srow]=b1v.z; Bs[BUF][sq*4+7][srow]=b1v.w;
#define Q_COMP(BUF) \
    _Pragma("unroll") \
    for (int kk = 0; kk < 16; kk++) { \
        float4 a0 = *(const float4*)&As[BUF][kk][ty * 8]; \
        float4 a1 = *(const float4*)&As[BUF][kk][ty * 8 + 4]; \
        float4 b0 = *(const float4*)&Bs[BUF][kk][tx * 8]; \
        float4 b1 = *(const float4*)&Bs[BUF][kk][tx * 8 + 4]; \
        MICRO8X8(acc2, a0, a1, b0, b1) \
    }

    Q_LDG(0) Q_STS(0)
    __syncthreads();
    for (int kt = 0; kt < 32; kt += 2) {
        if (kt + 1 < 32) { Q_LDG(kt + 1) }
        Q_COMP(0)
        if (kt + 1 < 32) { Q_STS(1) }
        __syncthreads();
        if (kt + 1 < 32) {
            if (kt + 2 < 32) { Q_LDG(kt + 2) }
            Q_COMP(1)
            if (kt + 2 < 32) { Q_STS(0) }
            __syncthreads();
        }
    }

    float acc[8][8];
#pragma unroll
    for (int i = 0; i < 8; i++)
#pragma unroll
        for (int p = 0; p < 4; p++) unpack2(acc2[i][p], acc[i][2 * p], acc[i][2 * p + 1]);

    int m0 = blockIdx.y * 128 + ty * 8;
    int n0 = blockIdx.x * 128 + tx * 8;
#pragma unroll
    for (int i = 0; i < 8; i++) {
        int m = m0 + i;
        int b = m / Nn, n = m % Nn;
#pragma unroll
        for (int j = 0; j < 8; j++) {
            int jc = n0 + j;
            int part = jc / INNER, r = jc % INNER;
            int h = r / DH, d = r % DH;
            float* dst = (part == 0) ? g_Q : ((part == 1) ? g_K : g_V);
            dst[((size_t)(b * Hh + h) * Nn + n) * DH + d] = acc[i][j];
        }
    }
}

// ============================================================
// K2: per-token metric embeddings (unchanged)
// ============================================================
__global__ __launch_bounds__(256) void k_embed(const float* __restrict__ we, const float* __restrict__ be,
                                               const float* __restrict__ ws, const float* __restrict__ bs,
                                               const float* __restrict__ wh, const float* __restrict__ bhh) {
    __shared__ float W[Ff][65];
    __shared__ float bias[Ff];
    __shared__ float qr[4][64];
    __shared__ float raw[4][Ff];
    int tid = threadIdx.x;
    for (int i = tid; i < 64 * 64; i += 256) { W[i / 64][i % 64] = we[i]; W[64 + i / 64][i % 64] = ws[i]; }
    for (int i = tid; i < 32 * 64; i += 256) W[128 + i / 64][i % 64] = wh[i];
    for (int i = tid; i < Ff; i += 256) bias[i] = (i < 64) ? be[i] : ((i < 128) ? bs[i - 64] : bhh[i - 128]);
    const float* src = (blockIdx.y == 0) ? g_Q : g_K;
    int tok0 = blockIdx.x * 4;
    for (int i = tid; i < 4 * 64; i += 256) qr[i / 64][i % 64] = src[(size_t)(tok0 + i / 64) * 64 + (i % 64)];
    __syncthreads();
    for (int i = tid; i < 4 * Ff; i += 256) {
        int tt = i / Ff, j = i % Ff;
        float s = bias[j];
#pragma unroll 8
        for (int c = 0; c < 64; c++) s += qr[tt][c] * W[j][c];
        raw[tt][j] = s;
    }
    __syncthreads();
    int w = tid >> 5, lane = tid & 31;
    if (w < 4) {
        int tt = w;
        float an = 0.f, sn = 0.f, un = 0.f;
        for (int j = lane; j < 64; j += 32) { float v = raw[tt][j]; an += v * v; }
        for (int j = 64 + lane; j < 128; j += 32) { float v = raw[tt][j]; sn += v * v; }
        {
            int j = 128 + lane;
            float th = tanhf(raw[tt][j]);
            raw[tt][j] = th;
            un += th * th;
        }
#pragma unroll
        for (int o = 16; o; o >>= 1) {
            an += __shfl_xor_sync(0xffffffffu, an, o);
            sn += __shfl_xor_sync(0xffffffffu, sn, o);
            un += __shfl_xor_sync(0xffffffffu, un, o);
        }
        float inv = 1.f / fmaxf(sqrtf(sn), 1e-12f);
        __syncwarp();
        float* Fdst = (blockIdx.y == 0) ? g_FQ : g_FK;
        int tok = tok0 + tt;
        for (int j = lane; j < Ff; j += 32) {
            float v = raw[tt][j];
            if (j >= 64 && j < 128) v *= inv;
            Fdst[(size_t)tok * Ff + j] = v;
        }
        if (lane == 0) {
            if (blockIdx.y == 0) { g_QA[tok] = an; g_QU[tok] = un; }
            else                 { g_KB[tok] = an; g_KV[tok] = un; }
        }
    }
}

// ============================================================
// K3: FUSED attention, SPLIT-K, shift-free softmax (scores <= 0).
// ============================================================
#define O_ARES 0        // 160 x 68
#define O_BS   10880    // 2 x 32 x 68
#define O_PS   15232    // 64 x 68
#define O_VS   19584    // 64 x 68
#define O_AN   23936
#define O_UN   24000
#define O_BN   24064
#define O_VN   24128
#define ATT_SMEM_BYTES (24192 * 4)   // 96768 B

#define FMA16(ACC, a, b) \
    ACC[0][0] += a.x * b.x; ACC[0][1] += a.x * b.y; ACC[0][2] += a.x * b.z; ACC[0][3] += a.x * b.w; \
    ACC[1][0] += a.y * b.x; ACC[1][1] += a.y * b.y; ACC[1][2] += a.y * b.z; ACC[1][3] += a.y * b.w; \
    ACC[2][0] += a.z * b.x; ACC[2][1] += a.z * b.y; ACC[2][2] += a.z * b.z; ACC[2][3] += a.z * b.w; \
    ACC[3][0] += a.w * b.x; ACC[3][1] += a.w * b.y; ACC[3][2] += a.w * b.z; ACC[3][3] += a.w * b.w;

#define G2STEP(E, VB) { \
    accO[0][0]+=pa0.E*VB.x; accO[0][1]+=pa0.E*VB.y; accO[0][2]+=pa0.E*VB.z; accO[0][3]+=pa0.E*VB.w; \
    accO[1][0]+=pa1.E*VB.x; accO[1][1]+=pa1.E*VB.y; accO[1][2]+=pa1.E*VB.z; accO[1][3]+=pa1.E*VB.w; \
    accO[2][0]+=pa2.E*VB.x; accO[2][1]+=pa2.E*VB.y; accO[2][2]+=pa2.E*VB.z; accO[2][3]+=pa2.E*VB.w; \
    accO[3][0]+=pa3.E*VB.x; accO[3][1]+=pa3.E*VB.y; accO[3][2]+=pa3.E*VB.z; accO[3][3]+=pa3.E*VB.w; }

__global__ __launch_bounds__(256, 2) void k_attn(const float* __restrict__ alpha,
                                                 const float* __restrict__ beta,
                                                 const float* __restrict__ gamma,
                                                 const float* __restrict__ temp) {
    extern __shared__ float sm[];
    int tid = threadIdx.x;
    int ty = tid >> 4, tx = tid & 15;
    int brow = tid >> 2, bq = tid & 3;
    int bh = blockIdx.y;
    int row0 = blockIdx.x * 64;
    int part = blockIdx.z;

    const float* FQb = g_FQ + ((size_t)bh * Nn + row0) * Ff;
    const float* FKb = g_FK + (size_t)bh * Nn * Ff;
    const float* Vb  = g_V + (size_t)bh * Nn * DH;

#pragma unroll
    for (int t = 0; t < 10; t++) {
        int idx = tid + 256 * t;
        int r = idx / 40, q4 = idx % 40;
        float4 v = *(const float4*)(FQb + (size_t)r * Ff + q4 * 4);
        sm[O_ARES + (q4 * 4 + 0) * 68 + r] = v.x;
        sm[O_ARES + (q4 * 4 + 1) * 68 + r] = v.y;
        sm[O_ARES + (q4 * 4 + 2) * 68 + r] = v.z;
        sm[O_ARES + (q4 * 4 + 3) * 68 + r] = v.w;
    }
    if (tid < 64) {
        sm[O_AN + tid] = g_QA[bh * Nn + row0 + tid];
        sm[O_UN + tid] = g_QU[bh * Nn + row0 + tid];
    }

    float cE = softplusf(alpha[0]);
    float cS = softplusf(beta[0]);
    float cH = softplusf(gamma[0]);
    float negInvT = -1.f / softplusf(temp[0]);

    float l_[4], accO[4][4];
#pragma unroll
    for (int i = 0; i < 4; i++) {
        l_[i] = 0.f;
#pragma unroll
        for (int j = 0; j < 4; j++) accO[i][j] = 0.f;
    }
    __syncthreads();

    for (int kt = part * 4; kt < part * 4 + 4; kt++) {
        int col0 = kt * 64;
        const float* Bp = FKb + (size_t)(col0 + brow) * Ff + bq * 4;

        {
            float4 v0 = *(const float4*)(Bp);
            float4 v1 = *(const float4*)(Bp + 16);
            sm[O_BS + (bq * 4 + 0) * 68 + brow] = v0.x;
            sm[O_BS + (bq * 4 + 1) * 68 + brow] = v0.y;
            sm[O_BS + (bq * 4 + 2) * 68 + brow] = v0.z;
            sm[O_BS + (bq * 4 + 3) * 68 + brow] = v0.w;
            sm[O_BS + (bq * 4 + 16) * 68 + brow] = v1.x;
            sm[O_BS + (bq * 4 + 17) * 68 + brow] = v1.y;
            sm[O_BS + (bq * 4 + 18) * 68 + brow] = v1.z;
            sm[O_BS + (bq * 4 + 19) * 68 + brow] = v1.w;
        }
        if (tid < 64) {
            sm[O_BN + tid] = g_KB[bh * Nn + col0 + tid];
            sm[O_VN + tid] = g_KV[bh * Nn + col0 + tid];
        }
        __syncthreads();

        float acc[4][4] = {};
        float s_[4][4];
        float4 bvreg0, bvreg1;

#pragma unroll
        for (int c = 0; c < 5; c++) {
            if (c < 4) {
                bvreg0 = *(const float4*)(Bp + (c + 1) * 32);
                bvreg1 = *(const float4*)(Bp + (c + 1) * 32 + 16);
            }
            int bb = O_BS + (c & 1) * 2176;
#pragma unroll
            for (int kk = 0; kk < 32; kk++) {
                float4 a = *(const float4*)&sm[O_ARES + (c * 32 + kk) * 68 + ty * 4];
                float4 b = *(const float4*)&sm[bb + kk * 68 + tx * 4];
                FMA16(acc, a, b)
            }
            if (c < 4) {
                int b2 = O_BS + ((c + 1) & 1) * 2176;
                sm[b2 + (bq * 4 + 0) * 68 + brow] = bvreg0.x;
                sm[b2 + (bq * 4 + 1) * 68 + brow] = bvreg0.y;
                sm[b2 + (bq * 4 + 2) * 68 + brow] = bvreg0.z;
                sm[b2 + (bq * 4 + 3) * 68 + brow] = bvreg0.w;
                sm[b2 + (bq * 4 + 16) * 68 + brow] = bvreg1.x;
                sm[b2 + (bq * 4 + 17) * 68 + brow] = bvreg1.y;
                sm[b2 + (bq * 4 + 18) * 68 + brow] = bvreg1.z;
                sm[b2 + (bq * 4 + 19) * 68 + brow] = bvreg1.w;
            }
            if (c == 1) {
#pragma unroll
                for (int i = 0; i < 4; i++) {
                    float an = sm[O_AN + ty * 4 + i];
#pragma unroll
                    for (int j = 0; j < 4; j++) {
                        float bn = sm[O_BN + tx * 4 + j];
                        s_[i][j] = cE * fast_sqrt(fmaxf(an + bn - 2.f * acc[i][j], 1e-12f));
                        acc[i][j] = 0.f;
                    }
                }
            }
            if (c == 3) {
#pragma unroll
                for (int i = 0; i < 4; i++)
#pragma unroll
                    for (int j = 0; j < 4; j++) {
                        float x = fminf(fmaxf(acc[i][j], -1.f + 1e-6f), 1.f - 1e-6f);
                        float ax = fabsf(x);
                        float poly = fmaf(ax, fmaf(ax, fmaf(ax, -0.0187293f, 0.0742610f), -0.2121144f), 1.5707288f);
                        float rr = fast_sqrt(1.f - ax) * poly;
                        float dS = (x >= 0.f) ? rr : (3.14159265358979f - rr);
                        s_[i][j] += cS * dS;
                        acc[i][j] = 0.f;
                    }
            }
            if (c == 4) {
#pragma unroll
                for (int i = 0; i < 4; i++) {
                    float un = sm[O_UN + ty * 4 + i];
                    float one_m_un = 1.f - un;
#pragma unroll
                    for (int j = 0; j < 4; j++) {
                        float vn = sm[O_VN + tx * 4 + j];
                        float dns = fmaxf(un + vn - 2.f * acc[i][j], 0.f);
                        float denom = one_m_un * (1.f - vn) + 1e-8f;
                        float t = fmaxf(2.f * dns * fast_rcp(denom), 1e-6f);
                        float sh = fast_sqrt(t * (t + 2.f));
                        float dHp = __logf(1.f + t + sh);
                        s_[i][j] = negInvT * (s_[i][j] + cH * dHp);
                    }
                }
            }
            if (c < 4) __syncthreads();
        }

        // prefetch V tile into registers
        float4 vr[4];
#pragma unroll
        for (int t = 0; t < 4; t++) {
            int idx = tid + 256 * t;
            int c = idx >> 4, dq = idx & 15;
            vr[t] = *(const float4*)(Vb + (size_t)(col0 + c) * DH + dq * 4);
        }

        // shift-free softmax numerators: exp(s) directly (s <= 0, no overflow)
#pragma unroll
        for (int i = 0; i < 4; i++) {
            float p0 = __expf(s_[i][0]);
            float p1 = __expf(s_[i][1]);
            float p2 = __expf(s_[i][2]);
            float p3 = __expf(s_[i][3]);
            l_[i] += (p0 + p1) + (p2 + p3);
            *(float4*)&sm[O_PS + (ty * 4 + i) * 68 + tx * 4] = make_float4(p0, p1, p2, p3);
        }
#pragma unroll
        for (int t = 0; t < 4; t++) {
            int idx = tid + 256 * t;
            int c = idx >> 4, dq = idx & 15;
            *(float4*)&sm[O_VS + c * 68 + dq * 4] = vr[t];
        }
        __syncthreads();

        // P @ V accumulation
#pragma unroll
        for (int c4 = 0; c4 < 16; c4++) {
            float4 pa0 = *(const float4*)&sm[O_PS + (ty * 4 + 0) * 68 + c4 * 4];
            float4 pa1 = *(const float4*)&sm[O_PS + (ty * 4 + 1) * 68 + c4 * 4];
            float4 pa2 = *(const float4*)&sm[O_PS + (ty * 4 + 2) * 68 + c4 * 4];
            float4 pa3 = *(const float4*)&sm[O_PS + (ty * 4 + 3) * 68 + c4 * 4];
            float4 vb0 = *(const float4*)&sm[O_VS + (c4 * 4 + 0) * 68 + tx * 4];
            float4 vb1 = *(const float4*)&sm[O_VS + (c4 * 4 + 1) * 68 + tx * 4];
            float4 vb2 = *(const float4*)&sm[O_VS + (c4 * 4 + 2) * 68 + tx * 4];
            float4 vb3 = *(const float4*)&sm[O_VS + (c4 * 4 + 3) * 68 + tx * 4];
            G2STEP(x, vb0)
            G2STEP(y, vb1)
            G2STEP(z, vb2)
            G2STEP(w, vb3)
        }
        __syncthreads();
    }

    // single end-of-kernel row-sum reduction (16 tx lanes per row)
#pragma unroll
    for (int i = 0; i < 4; i++) {
#pragma unroll
        for (int o = 1; o < 16; o <<= 1) l_[i] += __shfl_xor_sync(0xffffffffu, l_[i], o);
    }

    // write unnormalized partials
#pragma unroll
    for (int i = 0; i < 4; i++) {
        int rowIdx = bh * Nn + row0 + ty * 4 + i;
        *(float4*)&g_Po[part][(size_t)rowIdx * DH + tx * 4] =
            make_float4(accO[i][0], accO[i][1], accO[i][2], accO[i][3]);
        if (tx == 0) g_Pl[part][rowIdx] = l_[i];
    }
}

// ============================================================
// K4: merge split-k partials (plain sums) -> g_O
// ============================================================
__global__ __launch_bounds__(256) void k_merge() {
    int tid = threadIdx.x;
    int rowIdx = blockIdx.x * 4 + (tid >> 6);
    int d = tid & 63;
    float L = g_Pl[0][rowIdx] + g_Pl[1][rowIdx] + g_Pl[2][rowIdx] + g_Pl[3][rowIdx];
    size_t base = (size_t)rowIdx * DH + d;
    float val = g_Po[0][base] + g_Po[1][base] + g_Po[2][base] + g_Po[3][base];
    int bh = rowIdx / Nn, n = rowIdx % Nn;
    int b = bh / Hh, h = bh % Hh;
    g_O[((size_t)(b * Nn + n)) * INNER + h * DH + d] = val * fast_rcp(L);
}

// ============================================================
// K6: final projection. 128x128 tile, 8x8 micro.
// ============================================================
__global__ __launch_bounds__(256) void k_proj(const float* __restrict__ wp,
                                              const float* __restrict__ bp,
                                              float* __restrict__ out) {
    __shared__ float As[2][16][LDA];
    __shared__ float Bs[2][16][LDA];
    int tid = threadIdx.x;
    int ty = tid >> 4, tx = tid & 15;
    int srow = tid >> 1, sq = (tid & 1) * 2;
    const float* Ap = g_O + ((size_t)(blockIdx.y * 128) + srow) * INNER + sq * 4;
    const float* Bp = wp + ((size_t)(blockIdx.x * 128) + srow) * INNER + sq * 4;
    u64 acc2[8][4] = {};
    float4 a0v, a1v, b0v, b1v;

#define P_LDG(KT) \
    a0v = *(const float4*)(Ap + (KT) * 16);     a1v = *(const float4*)(Ap + (KT) * 16 + 4); \
    b0v = *(const float4*)(Bp + (KT) * 16);     b1v = *(const float4*)(Bp + (KT) * 16 + 4);
#define P_STS(BUF) \
    As[BUF][sq*4+0][srow]=a0v.x; As[BUF][sq*4+1][srow]=a0v.y; As[BUF][sq*4+2][srow]=a0v.z; As[BUF][sq*4+3][srow]=a0v.w; \
    As[BUF][sq*4+4][srow]=a1v.x; As[BUF][sq*4+5][srow]=a1v.y; As[BUF][sq*4+6][srow]=a1v.z; As[BUF][sq*4+7][srow]=a1v.w; \
    Bs[BUF][sq*4+0][srow]=b0v.x; Bs[BUF][sq*4+1][srow]=b0v.y; Bs[BUF][sq*4+2][srow]=b0v.z; Bs[BUF][sq*4+3][srow]=b0v.w; \
    Bs[BUF][sq*4+4][srow]=b1v.x; Bs[BUF][sq*4+5][srow]=b1v.y; Bs[BUF][sq*4+6][srow]=b1v.z; Bs[BUF][sq*4+7][srow]=b1v.w;
#define P_COMP(BUF) \
    _Pragma("unroll") \
    for (int kk = 0; kk < 16; kk++) { \
        float4 a0 = *(const float4*)&As[BUF][kk][ty * 8]; \
        float4 a1 = *(const float4*)&As[BUF][kk][ty * 8 + 4]; \
        float4 b0 = *(const float4*)&Bs[BUF][kk][tx * 8]; \
        float4 b1 = *(const float4*)&Bs[BUF][kk][tx * 8 + 4]; \
        MICRO8X8(acc2, a0, a1, b0, b1) \
    }

    P_LDG(0) P_STS(0)
    __syncthreads();
    for (int kt = 0; kt < 32; kt += 2) {
        if (kt + 1 < 32) { P_LDG(kt + 1) }
        P_COMP(0)
        if (kt + 1 < 32) { P_STS(1) }
        __syncthreads();
        if (kt + 1 < 32) {
            if (kt + 2 < 32) { P_LDG(kt + 2) }
            P_COMP(1)
            if (kt + 2 < 32) { P_STS(0) }
            __syncthreads();
        }
    }

    int m0 = blockIdx.y * 128 + ty * 8;
    int n0 = blockIdx.x * 128 + tx * 8;
    float4 bias0 = *(const float4*)&bp[n0];
    float4 bias1 = *(const float4*)&bp[n0 + 4];
#pragma unroll
    for (int i = 0; i < 8; i++) {
        float4 o0, o1;
        unpack2(acc2[i][0], o0.x, o0.y); unpack2(acc2[i][1], o0.z, o0.w);
        unpack2(acc2[i][2], o1.x, o1.y); unpack2(acc2[i][3], o1.z, o1.w);
        o0.x += bias0.x; o0.y += bias0.y; o0.z += bias0.z; o0.w += bias0.w;
        o1.x += bias1.x; o1.y += bias1.y; o1.z += bias1.z; o1.w += bias1.w;
        *(float4*)&out[(size_t)(m0 + i) * Cc + n0] = o0;
        *(float4*)&out[(size_t)(m0 + i) * Cc + n0 + 4] = o1;
    }
}

extern "C" void kernel_launch(void* const* d_in, const int* in_sizes, int n_in,
                              void* d_out, int out_size) {
    const float* x      = (const float*)d_in[0];
    const float* w_qkv  = (const float*)d_in[1];
    const float* w_proj = (const float*)d_in[2];
    const float* b_proj = (const float*)d_in[3];
    const float* w_e    = (const float*)d_in[4];
    const float* b_e    = (const float*)d_in[5];
    const float* w_s    = (const float*)d_in[6];
    const float* b_s    = (const float*)d_in[7];
    const float* w_h    = (const float*)d_in[8];
    const float* b_h    = (const float*)d_in[9];
    const float* alpha  = (const float*)d_in[10];
    const float* beta   = (const float*)d_in[11];
    const float* gamma  = (const float*)d_in[12];
    const float* temp   = (const float*)d_in[13];
    float* out = (float*)d_out;

    cudaFuncSetAttribute(k_attn, cudaFuncAttributeMaxDynamicSharedMemorySize, ATT_SMEM_BYTES);

    k_qkv<<<dim3(12, 32), 256>>>(x, w_qkv);
    k_embed<<<dim3(BH * Nn / 4, 2), 256>>>(w_e, b_e, w_s, b_s, w_h, b_h);
    k_attn<<<dim3(16, BH, NPART), 256, ATT_SMEM_BYTES>>>(alpha, beta, gamma, temp);
    k_merge<<<BH * Nn / 4, 256>>>();
    k_proj<<<dim3(4, 32), 256>>>(w_proj, b_proj, out);
}

// round 14
// speedup vs baseline: 1.1149x; 1.0628x over previous
#include <cuda_runtime.h>
#include <cuda_bf16.h>
#include <math.h>
#include <stdint.h>

#define Bsz 4
#define Nn 1024
#define Cc 512
#define Hh 8
#define DH 64
#define BH 32
#define INNER 512
#define Ff 160   // 64 (E) + 64 (S) + 32 (H)
#define LDA 132  // smem stride for 128-wide tiles
#define NPART 4  // split-k parts (4 k-tiles each)

typedef unsigned long long u64;

// ---- scratch (static device allocations; no runtime alloc) ----
__device__ float g_Q[BH * Nn * DH];
__device__ float g_K[BH * Nn * DH];
__device__ float g_V[BH * Nn * DH];
__device__ float g_FQ[BH * Nn * Ff];
__device__ float g_FK[BH * Nn * Ff];
__device__ float g_QA[BH * Nn];
__device__ float g_QU[BH * Nn];
__device__ float g_KB[BH * Nn];
__device__ float g_KV[BH * Nn];
__device__ float g_O[Bsz * Nn * INNER];
// split-k partials (unnormalized; scores <= 0 so no max-tracking needed)
__device__ float g_Pl[NPART][BH * Nn];
__device__ float g_Po[NPART][(size_t)BH * Nn * DH];

__device__ __forceinline__ float softplusf(float x) {
    return (x > 20.f) ? x : log1pf(expf(x));
}
__device__ __forceinline__ float fast_sqrt(float x) {
    float r; asm("sqrt.approx.f32 %0, %1;" : "=f"(r) : "f"(x)); return r;
}
__device__ __forceinline__ float fast_rcp(float x) {
    float r; asm("rcp.approx.f32 %0, %1;" : "=f"(r) : "f"(x)); return r;
}

// ---- packed f32x2 FMA (ptxas splits to scalar FFMA; kept, codegen-neutral) ----
__device__ __forceinline__ void fma2(u64& d, u64 a, u64 b) {
    asm("fma.rn.f32x2 %0, %1, %2, %0;" : "+l"(d) : "l"(a), "l"(b));
}
__device__ __forceinline__ u64 pack2(float lo, float hi) {
    u64 r; asm("mov.b64 %0, {%1, %2};" : "=l"(r) : "f"(lo), "f"(hi)); return r;
}
__device__ __forceinline__ void unpack2(u64 v, float& lo, float& hi) {
    asm("mov.b64 {%0, %1}, %2;" : "=f"(lo), "=f"(hi) : "l"(v));
}

#define MICRO8X8(ACC2, a0, a1, b0, b1) {                                      \
    u64 q0 = pack2(b0.x, b0.y), q1 = pack2(b0.z, b0.w);                       \
    u64 q2 = pack2(b1.x, b1.y), q3 = pack2(b1.z, b1.w);                       \
    u64 ar;                                                                   \
    ar = pack2(a0.x, a0.x); fma2(ACC2[0][0],ar,q0); fma2(ACC2[0][1],ar,q1); fma2(ACC2[0][2],ar,q2); fma2(ACC2[0][3],ar,q3); \
    ar = pack2(a0.y, a0.y); fma2(ACC2[1][0],ar,q0); fma2(ACC2[1][1],ar,q1); fma2(ACC2[1][2],ar,q2); fma2(ACC2[1][3],ar,q3); \
    ar = pack2(a0.z, a0.z); fma2(ACC2[2][0],ar,q0); fma2(ACC2[2][1],ar,q1); fma2(ACC2[2][2],ar,q2); fma2(ACC2[2][3],ar,q3); \
    ar = pack2(a0.w, a0.w); fma2(ACC2[3][0],ar,q0); fma2(ACC2[3][1],ar,q1); fma2(ACC2[3][2],ar,q2); fma2(ACC2[3][3],ar,q3); \
    ar = pack2(a1.x, a1.x); fma2(ACC2[4][0],ar,q0); fma2(ACC2[4][1],ar,q1); fma2(ACC2[4][2],ar,q2); fma2(ACC2[4][3],ar,q3); \
    ar = pack2(a1.y, a1.y); fma2(ACC2[5][0],ar,q0); fma2(ACC2[5][1],ar,q1); fma2(ACC2[5][2],ar,q2); fma2(ACC2[5][3],ar,q3); \
    ar = pack2(a1.z, a1.z); fma2(ACC2[6][0],ar,q0); fma2(ACC2[6][1],ar,q1); fma2(ACC2[6][2],ar,q2); fma2(ACC2[6][3],ar,q3); \
    ar = pack2(a1.w, a1.w); fma2(ACC2[7][0],ar,q0); fma2(ACC2[7][1],ar,q1); fma2(ACC2[7][2],ar,q2); fma2(ACC2[7][3],ar,q3); \
}

// ============================================================
// K1: qkv = x @ w_qkv^T -> per-head Q/K/V. 128x128 tile, 8x8 micro.
// 2 CTAs/SM for latency hiding + better wave fit (384 CTAs).
// ============================================================
__global__ __launch_bounds__(256, 2) void k_qkv(const float* __restrict__ x,
                                                const float* __restrict__ w) {
    __shared__ float As[2][16][LDA];
    __shared__ float Bs[2][16][LDA];
    int tid = threadIdx.x;
    int ty = tid >> 4, tx = tid & 15;
    int srow = tid >> 1, sq = (tid & 1) * 2;
    const float* Ap = x + ((size_t)(blockIdx.y * 128) + srow) * Cc + sq * 4;
    const float* Bp = w + ((size_t)(blockIdx.x * 128) + srow) * Cc + sq * 4;
    u64 acc2[8][4] = {};
    float4 a0v, a1v, b0v, b1v;

#define Q_LDG(KT) \
    a0v = *(const float4*)(Ap + (KT) * 16);     a1v = *(const float4*)(Ap + (KT) * 16 + 4); \
    b0v = *(const float4*)(Bp + (KT) * 16);     b1v = *(const float4*)(Bp + (KT) * 16 + 4);
#define Q_STS(BUF) \
    As[BUF][sq*4+0][srow]=a0v.x; As[BUF][sq*4+1][srow]=a0v.y; As[BUF][sq*4+2][srow]=a0v.z; As[BUF][sq*4+3][srow]=a0v.w; \
    As[BUF][sq*4+4][srow]=a1v.x; As[BUF][sq*4+5][srow]=a1v.y; As[BUF][sq*4+6][srow]=a1v.z; As[BUF][sq*4+7][srow]=a1v.w; \
    Bs[BUF][sq*4+0][srow]=b0v.x; Bs[BUF][sq*4+1][srow]=b0v.y; Bs[BUF][sq*4+2][srow]=b0v.z; Bs[BUF][sq*4+3][srow]=b0v.w; \
    Bs[BUF][sq*4+4][srow]=b1v.x; Bs[BUF][sq*4+5][srow]=b1v.y; Bs[BUF][sq*4+6][srow]=b1v.z; Bs[BUF][sq*4+7][srow]=b1v.w;
#define Q_COMP(BUF) \
    _Pragma("unroll") \
    for (int kk = 0; kk < 16; kk++) { \
        float4 a0 = *(const float4*)&As[BUF][kk][ty * 8]; \
        float4 a1 = *(const float4*)&As[BUF][kk][ty * 8 + 4]; \
        float4 b0 = *(const float4*)&Bs[BUF][kk][tx * 8]; \
        float4 b1 = *(const float4*)&Bs[BUF][kk][tx * 8 + 4]; \
        MICRO8X8(acc2, a0, a1, b0, b1) \
    }

    Q_LDG(0) Q_STS(0)
    __syncthreads();
    for (int kt = 0; kt < 32; kt += 2) {
        if (kt + 1 < 32) { Q_LDG(kt + 1) }
        Q_COMP(0)
        if (kt + 1 < 32) { Q_STS(1) }
        __syncthreads();
        if (kt + 1 < 32) {
            if (kt + 2 < 32) { Q_LDG(kt + 2) }
            Q_COMP(1)
            if (kt + 2 < 32) { Q_STS(0) }
            __syncthreads();
        }
    }

    float acc[8][8];
#pragma unroll
    for (int i = 0; i < 8; i++)
#pragma unroll
        for (int p = 0; p < 4; p++) unpack2(acc2[i][p], acc[i][2 * p], acc[i][2 * p + 1]);

    int m0 = blockIdx.y * 128 + ty * 8;
    int n0 = blockIdx.x * 128 + tx * 8;
#pragma unroll
    for (int i = 0; i < 8; i++) {
        int m = m0 + i;
        int b = m / Nn, n = m % Nn;
#pragma unroll
        for (int j = 0; j < 8; j++) {
            int jc = n0 + j;
            int part = jc / INNER, r = jc % INNER;
            int h = r / DH, d = r % DH;
            float* dst = (part == 0) ? g_Q : ((part == 1) ? g_K : g_V);
            dst[((size_t)(b * Hh + h) * Nn + n) * DH + d] = acc[i][j];
        }
    }
}

// ============================================================
// K2: per-token metric embeddings. 16 tokens/block, dynamic smem.
// W re-load traffic cut 4x vs 4-token version.
// ============================================================
#define E_W    0        // 160 x 65
#define E_BIAS 10400    // 160
#define E_QR   10560    // 16 x 64
#define E_RAW  11584    // 16 x 160
#define EMB_SMEM ((11584 + 16 * 160) * 4)   // 56576 B

__global__ __launch_bounds__(256) void k_embed(const float* __restrict__ we, const float* __restrict__ be,
                                               const float* __restrict__ ws, const float* __restrict__ bs,
                                               const float* __restrict__ wh, const float* __restrict__ bhh) {
    extern __shared__ float es[];
    int tid = threadIdx.x;
    for (int i = tid; i < 64 * 64; i += 256) {
        es[E_W + (i / 64) * 65 + (i % 64)] = we[i];
        es[E_W + (64 + i / 64) * 65 + (i % 64)] = ws[i];
    }
    for (int i = tid; i < 32 * 64; i += 256)
        es[E_W + (128 + i / 64) * 65 + (i % 64)] = wh[i];
    for (int i = tid; i < Ff; i += 256)
        es[E_BIAS + i] = (i < 64) ? be[i] : ((i < 128) ? bs[i - 64] : bhh[i - 128]);
    const float* src = (blockIdx.y == 0) ? g_Q : g_K;
    int tok0 = blockIdx.x * 16;
    for (int i = tid; i < 16 * 64; i += 256)
        es[E_QR + i] = src[(size_t)tok0 * 64 + i];
    __syncthreads();
    for (int i = tid; i < 16 * Ff; i += 256) {
        int tt = i / Ff, j = i % Ff;
        float s = es[E_BIAS + j];
        const float* qrow = &es[E_QR + tt * 64];
        const float* wrow = &es[E_W + j * 65];
#pragma unroll 8
        for (int c = 0; c < 64; c++) s += qrow[c] * wrow[c];
        es[E_RAW + tt * Ff + j] = s;
    }
    __syncthreads();
    int w = tid >> 5, lane = tid & 31;
    float* Fdst = (blockIdx.y == 0) ? g_FQ : g_FK;
#pragma unroll
    for (int rep = 0; rep < 2; rep++) {
        int tt = w * 2 + rep;
        float* raw = &es[E_RAW + tt * Ff];
        float an = 0.f, sn = 0.f, un = 0.f;
        for (int j = lane; j < 64; j += 32) { float v = raw[j]; an += v * v; }
        for (int j = 64 + lane; j < 128; j += 32) { float v = raw[j]; sn += v * v; }
        {
            int j = 128 + lane;
            float th = tanhf(raw[j]);
            raw[j] = th;
            un += th * th;
        }
#pragma unroll
        for (int o = 16; o; o >>= 1) {
            an += __shfl_xor_sync(0xffffffffu, an, o);
            sn += __shfl_xor_sync(0xffffffffu, sn, o);
            un += __shfl_xor_sync(0xffffffffu, un, o);
        }
        float inv = 1.f / fmaxf(sqrtf(sn), 1e-12f);
        __syncwarp();
        int tok = tok0 + tt;
        for (int j = lane; j < Ff; j += 32) {
            float v = raw[j];
            if (j >= 64 && j < 128) v *= inv;
            Fdst[(size_t)tok * Ff + j] = v;
        }
        if (lane == 0) {
            if (blockIdx.y == 0) { g_QA[tok] = an; g_QU[tok] = un; }
            else                 { g_KB[tok] = an; g_KV[tok] = un; }
        }
    }
}

// ============================================================
// K3: FUSED attention, SPLIT-K, shift-free softmax (scores <= 0).
// ============================================================
#define O_ARES 0        // 160 x 68
#define O_BS   10880    // 2 x 32 x 68
#define O_PS   15232    // 64 x 68
#define O_VS   19584    // 64 x 68
#define O_AN   23936
#define O_UN   24000
#define O_BN   24064
#define O_VN   24128
#define ATT_SMEM_BYTES (24192 * 4)   // 96768 B

#define FMA16(ACC, a, b) \
    ACC[0][0] += a.x * b.x; ACC[0][1] += a.x * b.y; ACC[0][2] += a.x * b.z; ACC[0][3] += a.x * b.w; \
    ACC[1][0] += a.y * b.x; ACC[1][1] += a.y * b.y; ACC[1][2] += a.y * b.z; ACC[1][3] += a.y * b.w; \
    ACC[2][0] += a.z * b.x; ACC[2][1] += a.z * b.y; ACC[2][2] += a.z * b.z; ACC[2][3] += a.z * b.w; \
    ACC[3][0] += a.w * b.x; ACC[3][1] += a.w * b.y; ACC[3][2] += a.w * b.z; ACC[3][3] += a.w * b.w;

#define G2STEP(E, VB) { \
    accO[0][0]+=pa0.E*VB.x; accO[0][1]+=pa0.E*VB.y; accO[0][2]+=pa0.E*VB.z; accO[0][3]+=pa0.E*VB.w; \
    accO[1][0]+=pa1.E*VB.x; accO[1][1]+=pa1.E*VB.y; accO[1][2]+=pa1.E*VB.z; accO[1][3]+=pa1.E*VB.w; \
    accO[2][0]+=pa2.E*VB.x; accO[2][1]+=pa2.E*VB.y; accO[2][2]+=pa2.E*VB.z; accO[2][3]+=pa2.E*VB.w; \
    accO[3][0]+=pa3.E*VB.x; accO[3][1]+=pa3.E*VB.y; accO[3][2]+=pa3.E*VB.z; accO[3][3]+=pa3.E*VB.w; }

__global__ __launch_bounds__(256, 2) void k_attn(const float* __restrict__ alpha,
                                                 const float* __restrict__ beta,
                                                 const float* __restrict__ gamma,
                                                 const float* __restrict__ temp) {
    extern __shared__ float sm[];
    int tid = threadIdx.x;
    int ty = tid >> 4, tx = tid & 15;
    int brow = tid >> 2, bq = tid & 3;
    int bh = blockIdx.y;
    int row0 = blockIdx.x * 64;
    int part = blockIdx.z;

    const float* FQb = g_FQ + ((size_t)bh * Nn + row0) * Ff;
    const float* FKb = g_FK + (size_t)bh * Nn * Ff;
    const float* Vb  = g_V + (size_t)bh * Nn * DH;

#pragma unroll
    for (int t = 0; t < 10; t++) {
        int idx = tid + 256 * t;
        int r = idx / 40, q4 = idx % 40;
        float4 v = *(const float4*)(FQb + (size_t)r * Ff + q4 * 4);
        sm[O_ARES + (q4 * 4 + 0) * 68 + r] = v.x;
        sm[O_ARES + (q4 * 4 + 1) * 68 + r] = v.y;
        sm[O_ARES + (q4 * 4 + 2) * 68 + r] = v.z;
        sm[O_ARES + (q4 * 4 + 3) * 68 + r] = v.w;
    }
    if (tid < 64) {
        sm[O_AN + tid] = g_QA[bh * Nn + row0 + tid];
        sm[O_UN + tid] = g_QU[bh * Nn + row0 + tid];
    }

    float cE = softplusf(alpha[0]);
    float cS = softplusf(beta[0]);
    float cH = softplusf(gamma[0]);
    float negInvT = -1.f / softplusf(temp[0]);

    float l_[4], accO[4][4];
#pragma unroll
    for (int i = 0; i < 4; i++) {
        l_[i] = 0.f;
#pragma unroll
        for (int j = 0; j < 4; j++) accO[i][j] = 0.f;
    }
    __syncthreads();

    for (int kt = part * 4; kt < part * 4 + 4; kt++) {
        int col0 = kt * 64;
        const float* Bp = FKb + (size_t)(col0 + brow) * Ff + bq * 4;

        {
            float4 v0 = *(const float4*)(Bp);
            float4 v1 = *(const float4*)(Bp + 16);
            sm[O_BS + (bq * 4 + 0) * 68 + brow] = v0.x;
            sm[O_BS + (bq * 4 + 1) * 68 + brow] = v0.y;
            sm[O_BS + (bq * 4 + 2) * 68 + brow] = v0.z;
            sm[O_BS + (bq * 4 + 3) * 68 + brow] = v0.w;
            sm[O_BS + (bq * 4 + 16) * 68 + brow] = v1.x;
            sm[O_BS + (bq * 4 + 17) * 68 + brow] = v1.y;
            sm[O_BS + (bq * 4 + 18) * 68 + brow] = v1.z;
            sm[O_BS + (bq * 4 + 19) * 68 + brow] = v1.w;
        }
        if (tid < 64) {
            sm[O_BN + tid] = g_KB[bh * Nn + col0 + tid];
            sm[O_VN + tid] = g_KV[bh * Nn + col0 + tid];
        }
        __syncthreads();

        float acc[4][4] = {};
        float s_[4][4];
        float4 bvreg0, bvreg1;

#pragma unroll
        for (int c = 0; c < 5; c++) {
            if (c < 4) {
                bvreg0 = *(const float4*)(Bp + (c + 1) * 32);
                bvreg1 = *(const float4*)(Bp + (c + 1) * 32 + 16);
            }
            int bb = O_BS + (c & 1) * 2176;
#pragma unroll
            for (int kk = 0; kk < 32; kk++) {
                float4 a = *(const float4*)&sm[O_ARES + (c * 32 + kk) * 68 + ty * 4];
                float4 b = *(const float4*)&sm[bb + kk * 68 + tx * 4];
                FMA16(acc, a, b)
            }
            if (c < 4) {
                int b2 = O_BS + ((c + 1) & 1) * 2176;
                sm[b2 + (bq * 4 + 0) * 68 + brow] = bvreg0.x;
                sm[b2 + (bq * 4 + 1) * 68 + brow] = bvreg0.y;
                sm[b2 + (bq * 4 + 2) * 68 + brow] = bvreg0.z;
                sm[b2 + (bq * 4 + 3) * 68 + brow] = bvreg0.w;
                sm[b2 + (bq * 4 + 16) * 68 + brow] = bvreg1.x;
                sm[b2 + (bq * 4 + 17) * 68 + brow] = bvreg1.y;
                sm[b2 + (bq * 4 + 18) * 68 + brow] = bvreg1.z;
                sm[b2 + (bq * 4 + 19) * 68 + brow] = bvreg1.w;
            }
            if (c == 1) {
#pragma unroll
                for (int i = 0; i < 4; i++) {
                    float an = sm[O_AN + ty * 4 + i];
#pragma unroll
                    for (int j = 0; j < 4; j++) {
                        float bn = sm[O_BN + tx * 4 + j];
                        s_[i][j] = cE * fast_sqrt(fmaxf(an + bn - 2.f * acc[i][j], 1e-12f));
                        acc[i][j] = 0.f;
                    }
                }
            }
            if (c == 3) {
#pragma unroll
                for (int i = 0; i < 4; i++)
#pragma unroll
                    for (int j = 0; j < 4; j++) {
                        float x = fminf(fmaxf(acc[i][j], -1.f + 1e-6f), 1.f - 1e-6f);
                        float ax = fabsf(x);
                        float poly = fmaf(ax, fmaf(ax, fmaf(ax, -0.0187293f, 0.0742610f), -0.2121144f), 1.5707288f);
                        float rr = fast_sqrt(1.f - ax) * poly;
                        float dS = (x >= 0.f) ? rr : (3.14159265358979f - rr);
                        s_[i][j] += cS * dS;
                        acc[i][j] = 0.f;
                    }
            }
            if (c == 4) {
#pragma unroll
                for (int i = 0; i < 4; i++) {
                    float un = sm[O_UN + ty * 4 + i];
                    float one_m_un = 1.f - un;
#pragma unroll
                    for (int j = 0; j < 4; j++) {
                        float vn = sm[O_VN + tx * 4 + j];
                        float dns = fmaxf(un + vn - 2.f * acc[i][j], 0.f);
                        float denom = one_m_un * (1.f - vn) + 1e-8f;
                        float t = fmaxf(2.f * dns * fast_rcp(denom), 1e-6f);
                        float sh = fast_sqrt(t * (t + 2.f));
                        float dHp = __logf(1.f + t + sh);
                        s_[i][j] = negInvT * (s_[i][j] + cH * dHp);
                    }
                }
            }
            if (c < 4) __syncthreads();
        }

        float4 vr[4];
#pragma unroll
        for (int t = 0; t < 4; t++) {
            int idx = tid + 256 * t;
            int c = idx >> 4, dq = idx & 15;
            vr[t] = *(const float4*)(Vb + (size_t)(col0 + c) * DH + dq * 4);
        }

#pragma unroll
        for (int i = 0; i < 4; i++) {
            float p0 = __expf(s_[i][0]);
            float p1 = __expf(s_[i][1]);
            float p2 = __expf(s_[i][2]);
            float p3 = __expf(s_[i][3]);
            l_[i] += (p0 + p1) + (p2 + p3);
            *(float4*)&sm[O_PS + (ty * 4 + i) * 68 + tx * 4] = make_float4(p0, p1, p2, p3);
        }
#pragma unroll
        for (int t = 0; t < 4; t++) {
            int idx = tid + 256 * t;
            int c = idx >> 4, dq = idx & 15;
            *(float4*)&sm[O_VS + c * 68 + dq * 4] = vr[t];
        }
        __syncthreads();

#pragma unroll
        for (int c4 = 0; c4 < 16; c4++) {
            float4 pa0 = *(const float4*)&sm[O_PS + (ty * 4 + 0) * 68 + c4 * 4];
            float4 pa1 = *(const float4*)&sm[O_PS + (ty * 4 + 1) * 68 + c4 * 4];
            float4 pa2 = *(const float4*)&sm[O_PS + (ty * 4 + 2) * 68 + c4 * 4];
            float4 pa3 = *(const float4*)&sm[O_PS + (ty * 4 + 3) * 68 + c4 * 4];
            float4 vb0 = *(const float4*)&sm[O_VS + (c4 * 4 + 0) * 68 + tx * 4];
            float4 vb1 = *(const float4*)&sm[O_VS + (c4 * 4 + 1) * 68 + tx * 4];
            float4 vb2 = *(const float4*)&sm[O_VS + (c4 * 4 + 2) * 68 + tx * 4];
            float4 vb3 = *(const float4*)&sm[O_VS + (c4 * 4 + 3) * 68 + tx * 4];
            G2STEP(x, vb0)
            G2STEP(y, vb1)
            G2STEP(z, vb2)
            G2STEP(w, vb3)
        }
        __syncthreads();
    }

#pragma unroll
    for (int i = 0; i < 4; i++) {
#pragma unroll
        for (int o = 1; o < 16; o <<= 1) l_[i] += __shfl_xor_sync(0xffffffffu, l_[i], o);
    }

#pragma unroll
    for (int i = 0; i < 4; i++) {
        int rowIdx = bh * Nn + row0 + ty * 4 + i;
        *(float4*)&g_Po[part][(size_t)rowIdx * DH + tx * 4] =
            make_float4(accO[i][0], accO[i][1], accO[i][2], accO[i][3]);
        if (tx == 0) g_Pl[part][rowIdx] = l_[i];
    }
}

// ============================================================
// K4: merge split-k partials (plain sums) -> g_O
// ============================================================
__global__ __launch_bounds__(256) void k_merge() {
    int tid = threadIdx.x;
    int rowIdx = blockIdx.x * 4 + (tid >> 6);
    int d = tid & 63;
    float L = g_Pl[0][rowIdx] + g_Pl[1][rowIdx] + g_Pl[2][rowIdx] + g_Pl[3][rowIdx];
    size_t base = (size_t)rowIdx * DH + d;
    float val = g_Po[0][base] + g_Po[1][base] + g_Po[2][base] + g_Po[3][base];
    int bh = rowIdx / Nn, n = rowIdx % Nn;
    int b = bh / Hh, h = bh % Hh;
    g_O[((size_t)(b * Nn + n)) * INNER + h * DH + d] = val * fast_rcp(L);
}

// ============================================================
// K6: final projection. 128x128 tile, 8x8 micro.
// ============================================================
__global__ __launch_bounds__(256) void k_proj(const float* __restrict__ wp,
                                              const float* __restrict__ bp,
                                              float* __restrict__ out) {
    __shared__ float As[2][16][LDA];
    __shared__ float Bs[2][16][LDA];
    int tid = threadIdx.x;
    int ty = tid >> 4, tx = tid & 15;
    int srow = tid >> 1, sq = (tid & 1) * 2;
    const float* Ap = g_O + ((size_t)(blockIdx.y * 128) + srow) * INNER + sq * 4;
    const float* Bp = wp + ((size_t)(blockIdx.x * 128) + srow) * INNER + sq * 4;
    u64 acc2[8][4] = {};
    float4 a0v, a1v, b0v, b1v;

#define P_LDG(KT) \
    a0v = *(const float4*)(Ap + (KT) * 16);     a1v = *(const float4*)(Ap + (KT) * 16 + 4); \
    b0v = *(const float4*)(Bp + (KT) * 16);     b1v = *(const float4*)(Bp + (KT) * 16 + 4);
#define P_STS(BUF) \
    As[BUF][sq*4+0][srow]=a0v.x; As[BUF][sq*4+1][srow]=a0v.y; As[BUF][sq*4+2][srow]=a0v.z; As[BUF][sq*4+3][srow]=a0v.w; \
    As[BUF][sq*4+4][srow]=a1v.x; As[BUF][sq*4+5][srow]=a1v.y; As[BUF][sq*4+6][srow]=a1v.z; As[BUF][sq*4+7][srow]=a1v.w; \
    Bs[BUF][sq*4+0][srow]=b0v.x; Bs[BUF][sq*4+1][srow]=b0v.y; Bs[BUF][sq*4+2][srow]=b0v.z; Bs[BUF][sq*4+3][srow]=b0v.w; \
    Bs[BUF][sq*4+4][srow]=b1v.x; Bs[BUF][sq*4+5][srow]=b1v.y; Bs[BUF][sq*4+6][srow]=b1v.z; Bs[BUF][sq*4+7][srow]=b1v.w;
#define P_COMP(BUF) \
    _Pragma("unroll") \
    for (int kk = 0; kk < 16; kk++) { \
        float4 a0 = *(const float4*)&As[BUF][kk][ty * 8]; \
        float4 a1 = *(const float4*)&As[BUF][kk][ty * 8 + 4]; \
        float4 b0 = *(const float4*)&Bs[BUF][kk][tx * 8]; \
        float4 b1 = *(const float4*)&Bs[BUF][kk][tx * 8 + 4]; \
        MICRO8X8(acc2, a0, a1, b0, b1) \
    }

    P_LDG(0) P_STS(0)
    __syncthreads();
    for (int kt = 0; kt < 32; kt += 2) {
        if (kt + 1 < 32) { P_LDG(kt + 1) }
        P_COMP(0)
        if (kt + 1 < 32) { P_STS(1) }
        __syncthreads();
        if (kt + 1 < 32) {
            if (kt + 2 < 32) { P_LDG(kt + 2) }
            P_COMP(1)
            if (kt + 2 < 32) { P_STS(0) }
            __syncthreads();
        }
    }

    int m0 = blockIdx.y * 128 + ty * 8;
    int n0 = blockIdx.x * 128 + tx * 8;
    float4 bias0 = *(const float4*)&bp[n0];
    float4 bias1 = *(const float4*)&bp[n0 + 4];
#pragma unroll
    for (int i = 0; i < 8; i++) {
        float4 o0, o1;
        unpack2(acc2[i][0], o0.x, o0.y); unpack2(acc2[i][1], o0.z, o0.w);
        unpack2(acc2[i][2], o1.x, o1.y); unpack2(acc2[i][3], o1.z, o1.w);
        o0.x += bias0.x; o0.y += bias0.y; o0.z += bias0.z; o0.w += bias0.w;
        o1.x += bias1.x; o1.y += bias1.y; o1.z += bias1.z; o1.w += bias1.w;
        *(float4*)&out[(size_t)(m0 + i) * Cc + n0] = o0;
        *(float4*)&out[(size_t)(m0 + i) * Cc + n0 + 4] = o1;
    }
}

extern "C" void kernel_launch(void* const* d_in, const int* in_sizes, int n_in,
                              void* d_out, int out_size) {
    const float* x      = (const float*)d_in[0];
    const float* w_qkv  = (const float*)d_in[1];
    const float* w_proj = (const float*)d_in[2];
    const float* b_proj = (const float*)d_in[3];
    const float* w_e    = (const float*)d_in[4];
    const float* b_e    = (const float*)d_in[5];
    const float* w_s    = (const float*)d_in[6];
    const float* b_s    = (const float*)d_in[7];
    const float* w_h    = (const float*)d_in[8];
    const float* b_h    = (const float*)d_in[9];
    const float* alpha  = (const float*)d_in[10];
    const float* beta   = (const float*)d_in[11];
    const float* gamma  = (const float*)d_in[12];
    const float* temp   = (const float*)d_in[13];
    float* out = (float*)d_out;

    cudaFuncSetAttribute(k_attn, cudaFuncAttributeMaxDynamicSharedMemorySize, ATT_SMEM_BYTES);
    cudaFuncSetAttribute(k_embed, cudaFuncAttributeMaxDynamicSharedMemorySize, EMB_SMEM);

    k_qkv<<<dim3(12, 32), 256>>>(x, w_qkv);
    k_embed<<<dim3(BH * Nn / 16, 2), 256, EMB_SMEM>>>(w_e, b_e, w_s, b_s, w_h, b_h);
    k_attn<<<dim3(16, BH, NPART), 256, ATT_SMEM_BYTES>>>(alpha, beta, gamma, temp);
    k_merge<<<BH * Nn / 4, 256>>>();
    k_proj<<<dim3(4, 32), 256>>>(w_proj, b_proj, out);
}

// round 17
// speedup vs baseline: 1.1241x; 1.0082x over previous
#include <cuda_runtime.h>
#include <cuda_bf16.h>
#include <math.h>
#include <stdint.h>

#define Bsz 4
#define Nn 1024
#define Cc 512
#define Hh 8
#define DH 64
#define BH 32
#define INNER 512
#define Ff 160   // 64 (E) + 64 (S) + 32 (H)
#define LDA 132  // smem stride for 128-wide tiles
#define LDB 68   // smem stride for 64-wide tiles
#define NPART 4  // split-k parts (4 k-tiles each)

typedef unsigned long long u64;

// ---- scratch (static device allocations; no runtime alloc) ----
__device__ float g_Q[BH * Nn * DH];
__device__ float g_K[BH * Nn * DH];
__device__ float g_V[BH * Nn * DH];
__device__ float g_FQ[BH * Nn * Ff];
__device__ float g_FK[BH * Nn * Ff];
__device__ float g_QA[BH * Nn];
__device__ float g_QU[BH * Nn];
__device__ float g_KB[BH * Nn];
__device__ float g_KV[BH * Nn];
__device__ float g_O[Bsz * Nn * INNER];
// split-k partials (unnormalized; scores <= 0 so no max-tracking needed)
__device__ float g_Pl[NPART][BH * Nn];
__device__ float g_Po[NPART][(size_t)BH * Nn * DH];

__device__ __forceinline__ float softplusf(float x) {
    return (x > 20.f) ? x : log1pf(expf(x));
}
__device__ __forceinline__ float fast_sqrt(float x) {
    float r; asm("sqrt.approx.f32 %0, %1;" : "=f"(r) : "f"(x)); return r;
}
__device__ __forceinline__ float fast_rcp(float x) {
    float r; asm("rcp.approx.f32 %0, %1;" : "=f"(r) : "f"(x)); return r;
}

// ---- packed f32x2 FMA (ptxas splits to scalar FFMA; kept, codegen-neutral) ----
__device__ __forceinline__ void fma2(u64& d, u64 a, u64 b) {
    asm("fma.rn.f32x2 %0, %1, %2, %0;" : "+l"(d) : "l"(a), "l"(b));
}
__device__ __forceinline__ u64 pack2(float lo, float hi) {
    u64 r; asm("mov.b64 %0, {%1, %2};" : "=l"(r) : "f"(lo), "f"(hi)); return r;
}
__device__ __forceinline__ void unpack2(u64 v, float& lo, float& hi) {
    asm("mov.b64 {%0, %1}, %2;" : "=f"(lo), "=f"(hi) : "l"(v));
}

#define MICRO8X8(ACC2, a0, a1, b0, b1) {                                      \
    u64 q0 = pack2(b0.x, b0.y), q1 = pack2(b0.z, b0.w);                       \
    u64 q2 = pack2(b1.x, b1.y), q3 = pack2(b1.z, b1.w);                       \
    u64 ar;                                                                   \
    ar = pack2(a0.x, a0.x); fma2(ACC2[0][0],ar,q0); fma2(ACC2[0][1],ar,q1); fma2(ACC2[0][2],ar,q2); fma2(ACC2[0][3],ar,q3); \
    ar = pack2(a0.y, a0.y); fma2(ACC2[1][0],ar,q0); fma2(ACC2[1][1],ar,q1); fma2(ACC2[1][2],ar,q2); fma2(ACC2[1][3],ar,q3); \
    ar = pack2(a0.z, a0.z); fma2(ACC2[2][0],ar,q0); fma2(ACC2[2][1],ar,q1); fma2(ACC2[2][2],ar,q2); fma2(ACC2[2][3],ar,q3); \
    ar = pack2(a0.w, a0.w); fma2(ACC2[3][0],ar,q0); fma2(ACC2[3][1],ar,q1); fma2(ACC2[3][2],ar,q2); fma2(ACC2[3][3],ar,q3); \
    ar = pack2(a1.x, a1.x); fma2(ACC2[4][0],ar,q0); fma2(ACC2[4][1],ar,q1); fma2(ACC2[4][2],ar,q2); fma2(ACC2[4][3],ar,q3); \
    ar = pack2(a1.y, a1.y); fma2(ACC2[5][0],ar,q0); fma2(ACC2[5][1],ar,q1); fma2(ACC2[5][2],ar,q2); fma2(ACC2[5][3],ar,q3); \
    ar = pack2(a1.z, a1.z); fma2(ACC2[6][0],ar,q0); fma2(ACC2[6][1],ar,q1); fma2(ACC2[6][2],ar,q2); fma2(ACC2[6][3],ar,q3); \
    ar = pack2(a1.w, a1.w); fma2(ACC2[7][0],ar,q0); fma2(ACC2[7][1],ar,q1); fma2(ACC2[7][2],ar,q2); fma2(ACC2[7][3],ar,q3); \
}

#define MICRO8X4F(ACC, a0, a1, b) {                                           \
    ACC[0][0]+=a0.x*b.x; ACC[0][1]+=a0.x*b.y; ACC[0][2]+=a0.x*b.z; ACC[0][3]+=a0.x*b.w; \
    ACC[1][0]+=a0.y*b.x; ACC[1][1]+=a0.y*b.y; ACC[1][2]+=a0.y*b.z; ACC[1][3]+=a0.y*b.w; \
    ACC[2][0]+=a0.z*b.x; ACC[2][1]+=a0.z*b.y; ACC[2][2]+=a0.z*b.z; ACC[2][3]+=a0.z*b.w; \
    ACC[3][0]+=a0.w*b.x; ACC[3][1]+=a0.w*b.y; ACC[3][2]+=a0.w*b.z; ACC[3][3]+=a0.w*b.w; \
    ACC[4][0]+=a1.x*b.x; ACC[4][1]+=a1.x*b.y; ACC[4][2]+=a1.x*b.z; ACC[4][3]+=a1.x*b.w; \
    ACC[5][0]+=a1.y*b.x; ACC[5][1]+=a1.y*b.y; ACC[5][2]+=a1.y*b.z; ACC[5][3]+=a1.y*b.w; \
    ACC[6][0]+=a1.z*b.x; ACC[6][1]+=a1.z*b.y; ACC[6][2]+=a1.z*b.z; ACC[6][3]+=a1.z*b.w; \
    ACC[7][0]+=a1.w*b.x; ACC[7][1]+=a1.w*b.y; ACC[7][2]+=a1.w*b.z; ACC[7][3]+=a1.w*b.w; \
}

// ============================================================
// K1: qkv = x @ w_qkv^T -> per-head Q/K/V. 128x128 tile, 8x8 micro, 2 CTAs/SM.
// ============================================================
__global__ __launch_bounds__(256, 2) void k_qkv(const float* __restrict__ x,
                                                const float* __restrict__ w) {
    __shared__ float As[2][16][LDA];
    __shared__ float Bs[2][16][LDA];
    int tid = threadIdx.x;
    int ty = tid >> 4, tx = tid & 15;
    int srow = tid >> 1, sq = (tid & 1) * 2;
    const float* Ap = x + ((size_t)(blockIdx.y * 128) + srow) * Cc + sq * 4;
    const float* Bp = w + ((size_t)(blockIdx.x * 128) + srow) * Cc + sq * 4;
    u64 acc2[8][4] = {};
    float4 a0v, a1v, b0v, b1v;

#define Q_LDG(KT) \
    a0v = *(const float4*)(Ap + (KT) * 16);     a1v = *(const float4*)(Ap + (KT) * 16 + 4); \
    b0v = *(const float4*)(Bp + (KT) * 16);     b1v = *(const float4*)(Bp + (KT) * 16 + 4);
#define Q_STS(BUF) \
    As[BUF][sq*4+0][srow]=a0v.x; As[BUF][sq*4+1][srow]=a0v.y; As[BUF][sq*4+2][srow]=a0v.z; As[BUF][sq*4+3][srow]=a0v.w; \
    As[BUF][sq*4+4][srow]=a1v.x; As[BUF][sq*4+5][srow]=a1v.y; As[BUF][sq*4+6][srow]=a1v.z; As[BUF][sq*4+7][srow]=a1v.w; \
    Bs[BUF][sq*4+0][srow]=b0v.x; Bs[BUF][sq*4+1][srow]=b0v.y; Bs[BUF][sq*4+2][srow]=b0v.z; Bs[BUF][sq*4+3][srow]=b0v.w; \
    Bs[BUF][sq*4+4][srow]=b1v.x; Bs[BUF][sq*4+5][srow]=b1v.y; Bs[BUF][sq*4+6][srow]=b1v.z; Bs[BUF][sq*4+7][srow]=b1v.w;
#define Q_COMP(BUF) \
    _Pragma("unroll") \
    for (int kk = 0; kk < 16; kk++) { \
        float4 a0 = *(const float4*)&As[BUF][kk][ty * 8]; \
        float4 a1 = *(const float4*)&As[BUF][kk][ty * 8 + 4]; \
        float4 b0 = *(const float4*)&Bs[BUF][kk][tx * 8]; \
        float4 b1 = *(const float4*)&Bs[BUF][kk][tx * 8 + 4]; \
        MICRO8X8(acc2, a0, a1, b0, b1) \
    }

    Q_LDG(0) Q_STS(0)
    __syncthreads();
    for (int kt = 0; kt < 32; kt += 2) {
        if (kt + 1 < 32) { Q_LDG(kt + 1) }
        Q_COMP(0)
        if (kt + 1 < 32) { Q_STS(1) }
        __syncthreads();
        if (kt + 1 < 32) {
            if (kt + 2 < 32) { Q_LDG(kt + 2) }
            Q_COMP(1)
            if (kt + 2 < 32) { Q_STS(0) }
            __syncthreads();
        }
    }

    float acc[8][8];
#pragma unroll
    for (int i = 0; i < 8; i++)
#pragma unroll
        for (int p = 0; p < 4; p++) unpack2(acc2[i][p], acc[i][2 * p], acc[i][2 * p + 1]);

    int m0 = blockIdx.y * 128 + ty * 8;
    int n0 = blockIdx.x * 128 + tx * 8;
#pragma unroll
    for (int i = 0; i < 8; i++) {
        int m = m0 + i;
        int b = m / Nn, n = m % Nn;
#pragma unroll
        for (int j = 0; j < 8; j++) {
            int jc = n0 + j;
            int part = jc / INNER, r = jc % INNER;
            int h = r / DH, d = r % DH;
            float* dst = (part == 0) ? g_Q : ((part == 1) ? g_K : g_V);
            dst[((size_t)(b * Hh + h) * Nn + n) * DH + d] = acc[i][j];
        }
    }
}

// ============================================================
// K2: per-token metric embeddings. 16 tokens/block, dynamic smem.
// ============================================================
#define E_W    0        // 160 x 65
#define E_BIAS 10400    // 160
#define E_QR   10560    // 16 x 64
#define E_RAW  11584    // 16 x 160
#define EMB_SMEM ((11584 + 16 * 160) * 4)   // 56576 B

__global__ __launch_bounds__(256) void k_embed(const float* __restrict__ we, const float* __restrict__ be,
                                               const float* __restrict__ ws, const float* __restrict__ bs,
                                               const float* __restrict__ wh, const float* __restrict__ bhh) {
    extern __shared__ float es[];
    int tid = threadIdx.x;
    for (int i = tid; i < 64 * 64; i += 256) {
        es[E_W + (i / 64) * 65 + (i % 64)] = we[i];
        es[E_W + (64 + i / 64) * 65 + (i % 64)] = ws[i];
    }
    for (int i = tid; i < 32 * 64; i += 256)
        es[E_W + (128 + i / 64) * 65 + (i % 64)] = wh[i];
    for (int i = tid; i < Ff; i += 256)
        es[E_BIAS + i] = (i < 64) ? be[i] : ((i < 128) ? bs[i - 64] : bhh[i - 128]);
    const float* src = (blockIdx.y == 0) ? g_Q : g_K;
    int tok0 = blockIdx.x * 16;
    for (int i = tid; i < 16 * 64; i += 256)
        es[E_QR + i] = src[(size_t)tok0 * 64 + i];
    __syncthreads();
    for (int i = tid; i < 16 * Ff; i += 256) {
        int tt = i / Ff, j = i % Ff;
        float s = es[E_BIAS + j];
        const float* qrow = &es[E_QR + tt * 64];
        const float* wrow = &es[E_W + j * 65];
#pragma unroll 8
        for (int c = 0; c < 64; c++) s += qrow[c] * wrow[c];
        es[E_RAW + tt * Ff + j] = s;
    }
    __syncthreads();
    int w = tid >> 5, lane = tid & 31;
    float* Fdst = (blockIdx.y == 0) ? g_FQ : g_FK;
#pragma unroll
    for (int rep = 0; rep < 2; rep++) {
        int tt = w * 2 + rep;
        float* raw = &es[E_RAW + tt * Ff];
        float an = 0.f, sn = 0.f, un = 0.f;
        for (int j = lane; j < 64; j += 32) { float v = raw[j]; an += v * v; }
        for (int j = 64 + lane; j < 128; j += 32) { float v = raw[j]; sn += v * v; }
        {
            int j = 128 + lane;
            float th = tanhf(raw[j]);
            raw[j] = th;
            un += th * th;
        }
#pragma unroll
        for (int o = 16; o; o >>= 1) {
            an += __shfl_xor_sync(0xffffffffu, an, o);
            sn += __shfl_xor_sync(0xffffffffu, sn, o);
            un += __shfl_xor_sync(0xffffffffu, un, o);
        }
        float inv = 1.f / fmaxf(sqrtf(sn), 1e-12f);
        __syncwarp();
        int tok = tok0 + tt;
        for (int j = lane; j < Ff; j += 32) {
            float v = raw[j];
            if (j >= 64 && j < 128) v *= inv;
            Fdst[(size_t)tok * Ff + j] = v;
        }
        if (lane == 0) {
            if (blockIdx.y == 0) { g_QA[tok] = an; g_QU[tok] = un; }
            else                 { g_KB[tok] = an; g_KV[tok] = un; }
        }
    }
}

// ============================================================
// K3: FUSED attention, SPLIT-K, shift-free softmax (scores <= 0).
// ============================================================
#define O_ARES 0        // 160 x 68
#define O_BS   10880    // 2 x 32 x 68
#define O_PS   15232    // 64 x 68
#define O_VS   19584    // 64 x 68
#define O_AN   23936
#define O_UN   24000
#define O_BN   24064
#define O_VN   24128
#define ATT_SMEM_BYTES (24192 * 4)   // 96768 B

#define FMA16(ACC, a, b) \
    ACC[0][0] += a.x * b.x; ACC[0][1] += a.x * b.y; ACC[0][2] += a.x * b.z; ACC[0][3] += a.x * b.w; \
    ACC[1][0] += a.y * b.x; ACC[1][1] += a.y * b.y; ACC[1][2] += a.y * b.z; ACC[1][3] += a.y * b.w; \
    ACC[2][0] += a.z * b.x; ACC[2][1] += a.z * b.y; ACC[2][2] += a.z * b.z; ACC[2][3] += a.z * b.w; \
    ACC[3][0] += a.w * b.x; ACC[3][1] += a.w * b.y; ACC[3][2] += a.w * b.z; ACC[3][3] += a.w * b.w;

#define G2STEP(E, VB) { \
    accO[0][0]+=pa0.E*VB.x; accO[0][1]+=pa0.E*VB.y; accO[0][2]+=pa0.E*VB.z; accO[0][3]+=pa0.E*VB.w; \
    accO[1][0]+=pa1.E*VB.x; accO[1][1]+=pa1.E*VB.y; accO[1][2]+=pa1.E*VB.z; accO[1][3]+=pa1.E*VB.w; \
    accO[2][0]+=pa2.E*VB.x; accO[2][1]+=pa2.E*VB.y; accO[2][2]+=pa2.E*VB.z; accO[2][3]+=pa2.E*VB.w; \
    accO[3][0]+=pa3.E*VB.x; accO[3][1]+=pa3.E*VB.y; accO[3][2]+=pa3.E*VB.z; accO[3][3]+=pa3.E*VB.w; }

__global__ __launch_bounds__(256, 2) void k_attn(const float* __restrict__ alpha,
                                                 const float* __restrict__ beta,
                                                 const float* __restrict__ gamma,
                                                 const float* __restrict__ temp) {
    extern __shared__ float sm[];
    int tid = threadIdx.x;
    int ty = tid >> 4, tx = tid & 15;
    int brow = tid >> 2, bq = tid & 3;
    int bh = blockIdx.y;
    int row0 = blockIdx.x * 64;
    int part = blockIdx.z;

    const float* FQb = g_FQ + ((size_t)bh * Nn + row0) * Ff;
    const float* FKb = g_FK + (size_t)bh * Nn * Ff;
    const float* Vb  = g_V + (size_t)bh * Nn * DH;

#pragma unroll
    for (int t = 0; t < 10; t++) {
        int idx = tid + 256 * t;
        int r = idx / 40, q4 = idx % 40;
        float4 v = *(const float4*)(FQb + (size_t)r * Ff + q4 * 4);
        sm[O_ARES + (q4 * 4 + 0) * 68 + r] = v.x;
        sm[O_ARES + (q4 * 4 + 1) * 68 + r] = v.y;
        sm[O_ARES + (q4 * 4 + 2) * 68 + r] = v.z;
        sm[O_ARES + (q4 * 4 + 3) * 68 + r] = v.w;
    }
    if (tid < 64) {
        sm[O_AN + tid] = g_QA[bh * Nn + row0 + tid];
        sm[O_UN + tid] = g_QU[bh * Nn + row0 + tid];
    }

    float cE = softplusf(alpha[0]);
    float cS = softplusf(beta[0]);
    float cH = softplusf(gamma[0]);
    float negInvT = -1.f / softplusf(temp[0]);

    float l_[4], accO[4][4];
#pragma unroll
    for (int i = 0; i < 4; i++) {
        l_[i] = 0.f;
#pragma unroll
        for (int j = 0; j < 4; j++) accO[i][j] = 0.f;
    }
    __syncthreads();

    for (int kt = part * 4; kt < part * 4 + 4; kt++) {
        int col0 = kt * 64;
        const float* Bp = FKb + (size_t)(col0 + brow) * Ff + bq * 4;

        {
            float4 v0 = *(const float4*)(Bp);
            float4 v1 = *(const float4*)(Bp + 16);
            sm[O_BS + (bq * 4 + 0) * 68 + brow] = v0.x;
            sm[O_BS + (bq * 4 + 1) * 68 + brow] = v0.y;
            sm[O_BS + (bq * 4 + 2) * 68 + brow] = v0.z;
            sm[O_BS + (bq * 4 + 3) * 68 + brow] = v0.w;
            sm[O_BS + (bq * 4 + 16) * 68 + brow] = v1.x;
            sm[O_BS + (bq * 4 + 17) * 68 + brow] = v1.y;
            sm[O_BS + (bq * 4 + 18) * 68 + brow] = v1.z;
            sm[O_BS + (bq * 4 + 19) * 68 + brow] = v1.w;
        }
        if (tid < 64) {
            sm[O_BN + tid] = g_KB[bh * Nn + col0 + tid];
            sm[O_VN + tid] = g_KV[bh * Nn + col0 + tid];
        }
        __syncthreads();

        float acc[4][4] = {};
        float s_[4][4];
        float4 bvreg0, bvreg1;

#pragma unroll
        for (int c = 0; c < 5; c++) {
            if (c < 4) {
                bvreg0 = *(const float4*)(Bp + (c + 1) * 32);
                bvreg1 = *(const float4*)(Bp + (c + 1) * 32 + 16);
            }
            int bb = O_BS + (c & 1) * 2176;
#pragma unroll
            for (int kk = 0; kk < 32; kk++) {
                float4 a = *(const float4*)&sm[O_ARES + (c * 32 + kk) * 68 + ty * 4];
                float4 b = *(const float4*)&sm[bb + kk * 68 + tx * 4];
                FMA16(acc, a, b)
            }
            if (c < 4) {
                int b2 = O_BS + ((c + 1) & 1) * 2176;
                sm[b2 + (bq * 4 + 0) * 68 + brow] = bvreg0.x;
                sm[b2 + (bq * 4 + 1) * 68 + brow] = bvreg0.y;
                sm[b2 + (bq * 4 + 2) * 68 + brow] = bvreg0.z;
                sm[b2 + (bq * 4 + 3) * 68 + brow] = bvreg0.w;
                sm[b2 + (bq * 4 + 16) * 68 + brow] = bvreg1.x;
                sm[b2 + (bq * 4 + 17) * 68 + brow] = bvreg1.y;
                sm[b2 + (bq * 4 + 18) * 68 + brow] = bvreg1.z;
                sm[b2 + (bq * 4 + 19) * 68 + brow] = bvreg1.w;
            }
            if (c == 1) {
#pragma unroll
                for (int i = 0; i < 4; i++) {
                    float an = sm[O_AN + ty * 4 + i];
#pragma unroll
                    for (int j = 0; j < 4; j++) {
                        float bn = sm[O_BN + tx * 4 + j];
                        s_[i][j] = cE * fast_sqrt(fmaxf(an + bn - 2.f * acc[i][j], 1e-12f));
                        acc[i][j] = 0.f;
                    }
                }
            }
            if (c == 3) {
#pragma unroll
                for (int i = 0; i < 4; i++)
#pragma unroll
                    for (int j = 0; j < 4; j++) {
                        float x = fminf(fmaxf(acc[i][j], -1.f + 1e-6f), 1.f - 1e-6f);
                        float ax = fabsf(x);
                        float poly = fmaf(ax, fmaf(ax, fmaf(ax, -0.0187293f, 0.0742610f), -0.2121144f), 1.5707288f);
                        float rr = fast_sqrt(1.f - ax) * poly;
                        float dS = (x >= 0.f) ? rr : (3.14159265358979f - rr);
                        s_[i][j] += cS * dS;
                        acc[i][j] = 0.f;
                    }
            }
            if (c == 4) {
#pragma unroll
                for (int i = 0; i < 4; i++) {
                    float un = sm[O_UN + ty * 4 + i];
                    float one_m_un = 1.f - un;
#pragma unroll
                    for (int j = 0; j < 4; j++) {
                        float vn = sm[O_VN + tx * 4 + j];
                        float dns = fmaxf(un + vn - 2.f * acc[i][j], 0.f);
                        float denom = one_m_un * (1.f - vn) + 1e-8f;
                        float t = fmaxf(2.f * dns * fast_rcp(denom), 1e-6f);
                        float sh = fast_sqrt(t * (t + 2.f));
                        float dHp = __logf(1.f + t + sh);
                        s_[i][j] = negInvT * (s_[i][j] + cH * dHp);
                    }
                }
            }
            if (c < 4) __syncthreads();
        }

        float4 vr[4];
#pragma unroll
        for (int t = 0; t < 4; t++) {
            int idx = tid + 256 * t;
            int c = idx >> 4, dq = idx & 15;
            vr[t] = *(const float4*)(Vb + (size_t)(col0 + c) * DH + dq * 4);
        }

#pragma unroll
        for (int i = 0; i < 4; i++) {
            float p0 = __expf(s_[i][0]);
            float p1 = __expf(s_[i][1]);
            float p2 = __expf(s_[i][2]);
            float p3 = __expf(s_[i][3]);
            l_[i] += (p0 + p1) + (p2 + p3);
            *(float4*)&sm[O_PS + (ty * 4 + i) * 68 + tx * 4] = make_float4(p0, p1, p2, p3);
        }
#pragma unroll
        for (int t = 0; t < 4; t++) {
            int idx = tid + 256 * t;
            int c = idx >> 4, dq = idx & 15;
            *(float4*)&sm[O_VS + c * 68 + dq * 4] = vr[t];
        }
        __syncthreads();

#pragma unroll
        for (int c4 = 0; c4 < 16; c4++) {
            float4 pa0 = *(const float4*)&sm[O_PS + (ty * 4 + 0) * 68 + c4 * 4];
            float4 pa1 = *(const float4*)&sm[O_PS + (ty * 4 + 1) * 68 + c4 * 4];
            float4 pa2 = *(const float4*)&sm[O_PS + (ty * 4 + 2) * 68 + c4 * 4];
            float4 pa3 = *(const float4*)&sm[O_PS + (ty * 4 + 3) * 68 + c4 * 4];
            float4 vb0 = *(const float4*)&sm[O_VS + (c4 * 4 + 0) * 68 + tx * 4];
            float4 vb1 = *(const float4*)&sm[O_VS + (c4 * 4 + 1) * 68 + tx * 4];
            float4 vb2 = *(const float4*)&sm[O_VS + (c4 * 4 + 2) * 68 + tx * 4];
            float4 vb3 = *(const float4*)&sm[O_VS + (c4 * 4 + 3) * 68 + tx * 4];
            G2STEP(x, vb0)
            G2STEP(y, vb1)
            G2STEP(z, vb2)
            G2STEP(w, vb3)
        }
        __syncthreads();
    }

#pragma unroll
    for (int i = 0; i < 4; i++) {
#pragma unroll
        for (int o = 1; o < 16; o <<= 1) l_[i] += __shfl_xor_sync(0xffffffffu, l_[i], o);
    }

#pragma unroll
    for (int i = 0; i < 4; i++) {
        int rowIdx = bh * Nn + row0 + ty * 4 + i;
        *(float4*)&g_Po[part][(size_t)rowIdx * DH + tx * 4] =
            make_float4(accO[i][0], accO[i][1], accO[i][2], accO[i][3]);
        if (tx == 0) g_Pl[part][rowIdx] = l_[i];
    }
}

// ============================================================
// K4: merge split-k partials (plain sums, float4 vectorized) -> g_O
// Each block: 16 rows; thread t -> row t>>4, d-quad t&15.
// ============================================================
__global__ __launch_bounds__(256) void k_merge() {
    int tid = threadIdx.x;
    int rowIdx = blockIdx.x * 16 + (tid >> 4);
    int dq = (tid & 15) * 4;
    float L = g_Pl[0][rowIdx] + g_Pl[1][rowIdx] + g_Pl[2][rowIdx] + g_Pl[3][rowIdx];
    size_t base = (size_t)rowIdx * DH + dq;
    float4 v0 = *(const float4*)&g_Po[0][base];
    float4 v1 = *(const float4*)&g_Po[1][base];
    float4 v2 = *(const float4*)&g_Po[2][base];
    float4 v3 = *(const float4*)&g_Po[3][base];
    float inv = fast_rcp(L);
    float4 o = make_float4((v0.x + v1.x + v2.x + v3.x) * inv,
                           (v0.y + v1.y + v2.y + v3.y) * inv,
                           (v0.z + v1.z + v2.z + v3.z) * inv,
                           (v0.w + v1.w + v2.w + v3.w) * inv);
    int bh = rowIdx / Nn, n = rowIdx % Nn;
    int b = bh / Hh, h = bh % Hh;
    *(float4*)&g_O[((size_t)(b * Nn + n)) * INNER + h * DH + dq] = o;
}

// ============================================================
// K6: final projection. 128x64 tile, 8x4 micro, grid 256 (better occupancy).
// ============================================================
__global__ __launch_bounds__(256) void k_proj(const float* __restrict__ wp,
                                              const float* __restrict__ bp,
                                              float* __restrict__ out) {
    __shared__ float As[2][16][LDA];
    __shared__ float Bs[2][16][LDB];
    int tid = threadIdx.x;
    int ty = tid >> 4, tx = tid & 15;
    int arow = tid >> 1, aq = (tid & 1) * 2;   // A: 128 rows x 2 float4
    int brow = tid >> 2, bqq = tid & 3;        // B: 64 rows x 4 float4
    const float* Ap = g_O + ((size_t)(blockIdx.y * 128) + arow) * INNER + aq * 4;
    const float* Bp = wp + ((size_t)(blockIdx.x * 64) + brow) * INNER + bqq * 4;
    float acc[8][4] = {};
    float4 a0v, a1v, bv;

#define P_LDG(KT) \
    a0v = *(const float4*)(Ap + (KT) * 16);     a1v = *(const float4*)(Ap + (KT) * 16 + 4); \
    bv  = *(const float4*)(Bp + (KT) * 16);
#define P_STS(BUF) \
    As[BUF][aq*4+0][arow]=a0v.x; As[BUF][aq*4+1][arow]=a0v.y; As[BUF][aq*4+2][arow]=a0v.z; As[BUF][aq*4+3][arow]=a0v.w; \
    As[BUF][aq*4+4][arow]=a1v.x; As[BUF][aq*4+5][arow]=a1v.y; As[BUF][aq*4+6][arow]=a1v.z; As[BUF][aq*4+7][arow]=a1v.w; \
    Bs[BUF][bqq*4+0][brow]=bv.x; Bs[BUF][bqq*4+1][brow]=bv.y; Bs[BUF][bqq*4+2][brow]=bv.z; Bs[BUF][bqq*4+3][brow]=bv.w;
#define P_COMP(BUF) \
    _Pragma("unroll") \
    for (int kk = 0; kk < 16; kk++) { \
        float4 a0 = *(const float4*)&As[BUF][kk][ty * 8]; \
        float4 a1 = *(const float4*)&As[BUF][kk][ty * 8 + 4]; \
        float4 b  = *(const float4*)&Bs[BUF][kk][tx * 4]; \
        MICRO8X4F(acc, a0, a1, b) \
    }

    P_LDG(0) P_STS(0)
    __syncthreads();
    for (int kt = 0; kt < 32; kt += 2) {
        if (kt + 1 < 32) { P_LDG(kt + 1) }
        P_COMP(0)
        if (kt + 1 < 32) { P_STS(1) }
        __syncthreads();
        if (kt + 1 < 32) {
            if (kt + 2 < 32) { P_LDG(kt + 2) }
            P_COMP(1)
            if (kt + 2 < 32) { P_STS(0) }
            __syncthreads();
        }
    }

    int m0 = blockIdx.y * 128 + ty * 8;
    int n0 = blockIdx.x * 64 + tx * 4;
    float4 bias = *(const float4*)&bp[n0];
#pragma unroll
    for (int i = 0; i < 8; i++) {
        float4 o = make_float4(acc[i][0] + bias.x, acc[i][1] + bias.y,
                               acc[i][2] + bias.z, acc[i][3] + bias.w);
        *(float4*)&out[(size_t)(m0 + i) * Cc + n0] = o;
    }
}

extern "C" void kernel_launch(void* const* d_in, const int* in_sizes, int n_in,
                              void* d_out, int out_size) {
    const float* x      = (const float*)d_in[0];
    const float* w_qkv  = (const float*)d_in[1];
    const float* w_proj = (const float*)d_in[2];
    const float* b_proj = (const float*)d_in[3];
    const float* w_e    = (const float*)d_in[4];
    const float* b_e    = (const float*)d_in[5];
    const float* w_s    = (const float*)d_in[6];
    const float* b_s    = (const float*)d_in[7];
    const float* w_h    = (const float*)d_in[8];
    const float* b_h    = (const float*)d_in[9];
    const float* alpha  = (const float*)d_in[10];
    const float* beta   = (const float*)d_in[11];
    const float* gamma  = (const float*)d_in[12];
    const float* temp   = (const float*)d_in[13];
    float* out = (float*)d_out;

    cudaFuncSetAttribute(k_attn, cudaFuncAttributeMaxDynamicSharedMemorySize, ATT_SMEM_BYTES);
    cudaFuncSetAttribute(k_embed, cudaFuncAttributeMaxDynamicSharedMemorySize, EMB_SMEM);

    k_qkv<<<dim3(12, 32), 256>>>(x, w_qkv);
    k_embed<<<dim3(BH * Nn / 16, 2), 256, EMB_SMEM>>>(w_e, b_e, w_s, b_s, w_h, b_h);
    k_attn<<<dim3(16, BH, NPART), 256, ATT_SMEM_BYTES>>>(alpha, beta, gamma, temp);
    k_merge<<<BH * Nn / 16, 256>>>();
    k_proj<<<dim3(8, 32), 256>>>(w_proj, b_proj, out);
}